// round 14
// baseline (speedup 1.0000x reference)
#include <cuda_runtime.h>
#include <cuda_bf16.h>
#include <cuda_fp16.h>

#define NC 4096
#define NH 8192
#define NT 12288
#define FD 512
#define RD 128
#define NL 3
#define NTILE (NH / 128)          // 64 S-tiles per row

typedef unsigned long long u64;
typedef unsigned int u32;

#define KC 64                     // k elements per chunk
#define TILE_B 16384              // 128 rows x 64 elems x 2B
#define GSMEM_B (2 * 4 * TILE_B)  // bf16-3 kernel: 2 stages x 4 tiles = 128KB
#define GSMEM_SX (2 * 2 * TILE_B) // sexp: 2 stages x (A,B) = 64KB
#define GSMEM_V  (3 * 2 * TILE_B) // vft: 3 stages x (A,B) = 96KB

// AV kernel tiling: BM=128, BN=128 minimizes L2 traffic
// traffic = P*(FD/BN) + VfT*(NC/BM) = 804MB + 806MB = 1.6GB (vs 3.6GB at 32x256)
#define AV_STAGE (2 * TILE_B)          // A 16KB + B 16KB
#define GSMEM_AV (2 * AV_STAGE)        // 64KB

static const float SCALE = 0.044194173824159216f;  // 1/sqrt(512)

// ---------------- helpers ----------------
__device__ __forceinline__ u32 smem_u32(const void* p) {
    u32 a;
    asm("{ .reg .u64 t; cvta.to.shared.u64 t, %1; cvt.u32.u64 %0, t; }" : "=r"(a) : "l"(p));
    return a;
}
__device__ __forceinline__ void ldsm4(u32* r, u32 addr) {
    asm volatile("ldmatrix.sync.aligned.m8n8.x4.shared.b16 {%0,%1,%2,%3}, [%4];"
                 : "=r"(r[0]), "=r"(r[1]), "=r"(r[2]), "=r"(r[3]) : "r"(addr));
}
__device__ __forceinline__ void mma_bf16(float* c, const u32* a, const u32* b) {
    asm volatile("mma.sync.aligned.m16n8k16.row.col.f32.bf16.bf16.f32 "
                 "{%0,%1,%2,%3}, {%4,%5,%6,%7}, {%8,%9}, {%0,%1,%2,%3};"
                 : "+f"(c[0]), "+f"(c[1]), "+f"(c[2]), "+f"(c[3])
                 : "r"(a[0]), "r"(a[1]), "r"(a[2]), "r"(a[3]), "r"(b[0]), "r"(b[1]));
}
__device__ __forceinline__ void mma_f16(float* c, const u32* a, const u32* b) {
    asm volatile("mma.sync.aligned.m16n8k16.row.col.f32.f16.f16.f32 "
                 "{%0,%1,%2,%3}, {%4,%5,%6,%7}, {%8,%9}, {%0,%1,%2,%3};"
                 : "+f"(c[0]), "+f"(c[1]), "+f"(c[2]), "+f"(c[3])
                 : "r"(a[0]), "r"(a[1]), "r"(a[2]), "r"(a[3]), "r"(b[0]), "r"(b[1]));
}
// D = A*B + 0  (fresh accumulator: avoids explicit acc2 zeroing)
__device__ __forceinline__ void mma_f16_zc(float* c, const u32* a, const u32* b) {
    asm volatile("mma.sync.aligned.m16n8k16.row.col.f32.f16.f16.f32 "
                 "{%0,%1,%2,%3}, {%4,%5,%6,%7}, {%8,%9}, {%10,%11,%12,%13};"
                 : "=f"(c[0]), "=f"(c[1]), "=f"(c[2]), "=f"(c[3])
                 : "r"(a[0]), "r"(a[1]), "r"(a[2]), "r"(a[3]), "r"(b[0]), "r"(b[1]),
                   "f"(0.f), "f"(0.f), "f"(0.f), "f"(0.f));
}
__device__ __forceinline__ u32 swz(u32 base, u32 row, u32 k) {
    return base + row * 128 + ((((k >> 3) ^ (row & 7)) & 7) << 4);
}

// ---------------- scratch ----------------
__device__ __align__(128) __nv_bfloat16 g_Xhi[(size_t)NT * FD],  g_Xlo[(size_t)NT * FD];
__device__ __align__(128) __nv_bfloat16 g_W1hi[(size_t)NL * RD * FD], g_W1lo[(size_t)NL * RD * FD];
__device__ __align__(128) __nv_bfloat16 g_Ghi[(size_t)NL * RD * RD],  g_Glo[(size_t)NL * RD * RD];
__device__ __align__(128) __nv_bfloat16 g_Hhi[(size_t)NL * NT * RD],  g_Hlo[(size_t)NL * NT * RD];
__device__ __align__(128) __half        g_Wf16[(size_t)FD * NL * FD]; // Wf fp16
__device__ __align__(128) __half        g_X16 [(size_t)NH * FD];      // hist fp16
__device__ __align__(128) __half        g_Hhf[(size_t)NL * NH * RD];  // historical H, fp16
__device__ __align__(128) __half        g_Hcf[(size_t)NL * NC * RD];  // Hc*G*scale, fp16
__device__ __align__(128) __half        g_P  [(size_t)NL * NC * NH];  // exp(s - m_tile) per tile
__device__ __align__(128) float         g_M  [(size_t)NL * NTILE * NC];  // per-tile row max
__device__ __align__(128) float         g_Zp [(size_t)NL * NTILE * NC];  // per-tile row sums
__device__ __align__(128) float         g_F  [(size_t)NL * NTILE * NC];  // exp(M - m_row) / Z
__device__ __align__(128) __half        g_VfT[(size_t)NL * FD * NH];  // Wf_l @ hist^T
__device__ __align__(128) float         g_v  [NL * RD];
__device__ __align__(128) float         g_cv [NL * NH];

// ======================================================================
// Split-bf16 HMMA GEMM (3 products), z-batched: C = act(A@B^T + bias)
// OM 1: split out (rows<NC) + fp16 out (rows>=NC)   OM 2: fp16 out
// ======================================================================
template<bool RELU, int OM>
__global__ __launch_bounds__(256, 1)
void mm128b(const __nv_bfloat16* __restrict__ Ahi, const __nv_bfloat16* __restrict__ Alo,
            size_t zsA, int lda,
            const __nv_bfloat16* __restrict__ Bhi, const __nv_bfloat16* __restrict__ Blo,
            size_t zsB, int ldb,
            const float* __restrict__ bias, size_t zsBias,
            __nv_bfloat16* __restrict__ Chi, __nv_bfloat16* __restrict__ Clo,
            size_t zsC, int ldcs,
            __half* __restrict__ Ch, size_t zsCh, int ldch,
            int K)
{
    extern __shared__ __align__(1024) char smem[];
    const int tid  = threadIdx.x;
    const int wid  = tid >> 5;
    const int lane = tid & 31;
    const int z  = blockIdx.z;
    const int m0 = blockIdx.y * 128;
    const int n0 = blockIdx.x * 128;
    const int wm = (wid & 1) * 64;
    const int wn = (wid >> 1) * 32;

    const u32 sbase = smem_u32(smem);
    const __nv_bfloat16* srcs[4] = {
        Ahi + zsA * z + (size_t)m0 * lda, Alo + zsA * z + (size_t)m0 * lda,
        Bhi + zsB * z + (size_t)n0 * ldb, Blo + zsB * z + (size_t)n0 * ldb };
    const int lds[4] = { lda, lda, ldb, ldb };

    float acc[4][4][4];
#pragma unroll
    for (int i = 0; i < 4; ++i)
#pragma unroll
        for (int j = 0; j < 4; ++j)
#pragma unroll
            for (int h = 0; h < 4; ++h) acc[i][j][h] = 0.f;

    const u32 a_row = lane & 15;
    const u32 a_k   = (lane >> 4) << 3;
    const u32 b_row = ((lane >> 4) << 3) + (lane & 7);
    const u32 b_k   = ((lane >> 3) & 1) << 3;

    const int nch = K / KC;

    auto load_chunk = [&](int c, int buf) {
        const int kb = c * KC;
        const u32 sb = sbase + buf * 4 * TILE_B;
#pragma unroll
        for (int i = 0; i < 16; ++i) {
            const int t  = i >> 2;
            const int cc = ((i & 3) << 8) + tid;
            const int row = cc >> 3;
            const int k8  = cc & 7;
            const __nv_bfloat16* g = srcs[t] + (size_t)row * lds[t] + kb + (k8 << 3);
            const u32 d = sb + t * TILE_B + row * 128 + (((u32)k8 ^ ((u32)row & 7)) << 4);
            asm volatile("cp.async.cg.shared.global [%0], [%1], 16;" :: "r"(d), "l"(g));
        }
        asm volatile("cp.async.commit_group;" ::: "memory");
    };

    load_chunk(0, 0);

    for (int c = 0; c < nch; ++c) {
        if (c + 1 < nch) {
            load_chunk(c + 1, (c + 1) & 1);
            asm volatile("cp.async.wait_group 1;" ::: "memory");
        } else {
            asm volatile("cp.async.wait_group 0;" ::: "memory");
        }
        __syncthreads();

        const u32 sA_h = sbase + (c & 1) * 4 * TILE_B;
        const u32 sA_l = sA_h + TILE_B;
        const u32 sB_h = sA_h + 2 * TILE_B;
        const u32 sB_l = sA_h + 3 * TILE_B;

#pragma unroll
        for (int ks = 0; ks < 4; ++ks) {
            const u32 kb = ks << 4;
            u32 ah[4][4], al[4][4], bh[2][4], bl[2][4];
#pragma unroll
            for (int mt = 0; mt < 4; ++mt) {
                ldsm4(ah[mt], swz(sA_h, wm + mt * 16 + a_row, kb + a_k));
                ldsm4(al[mt], swz(sA_l, wm + mt * 16 + a_row, kb + a_k));
            }
#pragma unroll
            for (int np = 0; np < 2; ++np) {
                ldsm4(bh[np], swz(sB_h, wn + np * 16 + b_row, kb + b_k));
                ldsm4(bl[np], swz(sB_l, wn + np * 16 + b_row, kb + b_k));
            }
#pragma unroll
            for (int mt = 0; mt < 4; ++mt)
#pragma unroll
                for (int nt = 0; nt < 4; ++nt) {
                    const u32* bhp = &bh[nt >> 1][(nt & 1) * 2];
                    const u32* blp = &bl[nt >> 1][(nt & 1) * 2];
                    mma_bf16(acc[mt][nt], ah[mt], bhp);
                    mma_bf16(acc[mt][nt], ah[mt], blp);
                    mma_bf16(acc[mt][nt], al[mt], bhp);
                }
        }
        __syncthreads();
    }

    const int g  = lane >> 2;
    const int tg = lane & 3;
#pragma unroll
    for (int mt = 0; mt < 4; ++mt)
#pragma unroll
        for (int nt = 0; nt < 4; ++nt) {
            const int cc = n0 + wn + nt * 8 + tg * 2;
#pragma unroll
            for (int h = 0; h < 2; ++h) {
                const int r = m0 + wm + mt * 16 + g + h * 8;
                float v0 = acc[mt][nt][h * 2 + 0];
                float v1 = acc[mt][nt][h * 2 + 1];
                if (bias) { v0 += bias[zsBias * z + cc]; v1 += bias[zsBias * z + cc + 1]; }
                if (RELU) { v0 = fmaxf(v0, 0.f); v1 = fmaxf(v1, 0.f); }
                if (OM == 1) {
                    if (r < NC) {
                        __nv_bfloat16 h0 = __float2bfloat16(v0);
                        __nv_bfloat16 h1 = __float2bfloat16(v1);
                        *(__nv_bfloat162*)(Chi + zsC * z + (size_t)r * ldcs + cc) =
                            __halves2bfloat162(h0, h1);
                        *(__nv_bfloat162*)(Clo + zsC * z + (size_t)r * ldcs + cc) =
                            __halves2bfloat162(
                                __float2bfloat16(v0 - __bfloat162float(h0)),
                                __float2bfloat16(v1 - __bfloat162float(h1)));
                    } else {
                        *(__half2*)(Ch + zsCh * z + (size_t)(r - NC) * ldch + cc) =
                            __halves2half2(__float2half_rn(v0), __float2half_rn(v1));
                    }
                }
                if (OM == 2)
                    *(__half2*)(Ch + zsCh * z + (size_t)r * ldch + cc) =
                        __halves2half2(__float2half_rn(v0), __float2half_rn(v1));
            }
        }
}

// ======================================================================
// fp16 single-product GEMM for VfT: C[FD,NH] = Wf_l @ hist^T, fp16 out.
// ======================================================================
__global__ __launch_bounds__(256, 2)
void vft_k(const __half* __restrict__ A, const __half* __restrict__ B,
           __half* __restrict__ C)
{
    extern __shared__ __align__(1024) char smem[];
    const int tid  = threadIdx.x;
    const int wid  = tid >> 5;
    const int lane = tid & 31;
    const int z  = blockIdx.z;
    const int m0 = blockIdx.y * 128;     // FD rows
    const int n0 = blockIdx.x * 128;     // NH rows
    const int wm = (wid & 1) * 64;
    const int wn = (wid >> 1) * 32;

    const u32 sbase = smem_u32(smem);
    const __half* Asrc = A + (size_t)z * FD + (size_t)m0 * (NL * FD);  // lda = NL*FD
    const __half* Bsrc = B + (size_t)n0 * FD;                          // ldb = FD

    float acc[4][4][4];
#pragma unroll
    for (int i = 0; i < 4; ++i)
#pragma unroll
        for (int j = 0; j < 4; ++j)
#pragma unroll
            for (int h = 0; h < 4; ++h) acc[i][j][h] = 0.f;

    const u32 a_row = lane & 15;
    const u32 a_k   = (lane >> 4) << 3;
    const u32 b_row = ((lane >> 4) << 3) + (lane & 7);
    const u32 b_k   = ((lane >> 3) & 1) << 3;

    const int nch = FD / KC;   // 8

    auto load_chunk = [&](int c) {
        const int kb = c * KC;
        const u32 sb = sbase + (c % 3) * 2 * TILE_B;
#pragma unroll
        for (int i = 0; i < 8; ++i) {
            const int t  = i >> 2;
            const int cc = ((i & 3) << 8) + tid;
            const int row = cc >> 3;
            const int k8  = cc & 7;
            const __half* g = (t ? (Bsrc + (size_t)row * FD) : (Asrc + (size_t)row * (NL * FD)))
                              + kb + (k8 << 3);
            const u32 d = sb + t * TILE_B + row * 128 + (((u32)k8 ^ ((u32)row & 7)) << 4);
            asm volatile("cp.async.cg.shared.global [%0], [%1], 16;" :: "r"(d), "l"(g));
        }
        asm volatile("cp.async.commit_group;" ::: "memory");
    };

    load_chunk(0);
    load_chunk(1);

    for (int c = 0; c < nch; ++c) {
        if (c + 1 < nch) { asm volatile("cp.async.wait_group 1;" ::: "memory"); }
        else             { asm volatile("cp.async.wait_group 0;" ::: "memory"); }
        __syncthreads();
        if (c + 2 < nch) load_chunk(c + 2);

        const u32 sA = sbase + (c % 3) * 2 * TILE_B;
        const u32 sB = sA + TILE_B;
#pragma unroll
        for (int ks = 0; ks < 4; ++ks) {
            const u32 kb = ks << 4;
            u32 ah[4][4], bh[2][4];
#pragma unroll
            for (int mt = 0; mt < 4; ++mt)
                ldsm4(ah[mt], swz(sA, wm + mt * 16 + a_row, kb + a_k));
#pragma unroll
            for (int np = 0; np < 2; ++np)
                ldsm4(bh[np], swz(sB, wn + np * 16 + b_row, kb + b_k));
#pragma unroll
            for (int mt = 0; mt < 4; ++mt)
#pragma unroll
                for (int nt = 0; nt < 4; ++nt)
                    mma_f16(acc[mt][nt], ah[mt], &bh[nt >> 1][(nt & 1) * 2]);
        }
    }

    const int g  = lane >> 2;
    const int tg = lane & 3;
    __half* Cz = C + (size_t)z * FD * NH;
#pragma unroll
    for (int mt = 0; mt < 4; ++mt)
#pragma unroll
        for (int nt = 0; nt < 4; ++nt) {
            const int cc = n0 + wn + nt * 8 + tg * 2;
#pragma unroll
            for (int h = 0; h < 2; ++h) {
                const int r = m0 + wm + mt * 16 + g + h * 8;
                *(__half2*)(Cz + (size_t)r * NH + cc) =
                    __halves2half2(__float2half_rn(acc[mt][nt][h * 2 + 0]),
                                   __float2half_rn(acc[mt][nt][h * 2 + 1]));
            }
        }
}

// ======================================================================
// S+exp with per-tile row max (flash-style, overflow-proof):
// P_tile = exp(s - m_tile) fp16; M, Zp per (z, tile, row), no atomics.
// ======================================================================
__global__ __launch_bounds__(256, 2)
void sexp_k(const __half* __restrict__ Hcf, const __half* __restrict__ Hhf,
            const float* __restrict__ cv,
            __half* __restrict__ P, float* __restrict__ M, float* __restrict__ Zp)
{
    extern __shared__ __align__(1024) char smem[];
    __shared__ float wred[4][128];
    __shared__ float mrow[128];
    const int tid  = threadIdx.x;
    const int wid  = tid >> 5;
    const int lane = tid & 31;
    const int z  = blockIdx.z;
    const int m0 = blockIdx.y * 128;
    const int n0 = blockIdx.x * 128;
    const int wm = (wid & 1) * 64;
    const int wn = (wid >> 1) * 32;
    const int wcol = wid >> 1;

    const u32 sbase = smem_u32(smem);
    const __half* Asrc = Hcf + (size_t)z * NC * RD + (size_t)m0 * RD;
    const __half* Bsrc = Hhf + (size_t)z * NH * RD + (size_t)n0 * RD;

    float acc[4][4][4];
#pragma unroll
    for (int i = 0; i < 4; ++i)
#pragma unroll
        for (int j = 0; j < 4; ++j)
#pragma unroll
            for (int h = 0; h < 4; ++h) acc[i][j][h] = 0.f;

    const u32 a_row = lane & 15;
    const u32 a_k   = (lane >> 4) << 3;
    const u32 b_row = ((lane >> 4) << 3) + (lane & 7);
    const u32 b_k   = ((lane >> 3) & 1) << 3;

    auto load_chunk = [&](int c, int buf) {
        const int kb = c * KC;
        const u32 sb = sbase + buf * 2 * TILE_B;
#pragma unroll
        for (int i = 0; i < 8; ++i) {
            const int t  = i >> 2;
            const int cc = ((i & 3) << 8) + tid;
            const int row = cc >> 3;
            const int k8  = cc & 7;
            const __half* g = (t ? Bsrc : Asrc) + (size_t)row * RD + kb + (k8 << 3);
            const u32 d = sb + t * TILE_B + row * 128 + (((u32)k8 ^ ((u32)row & 7)) << 4);
            asm volatile("cp.async.cg.shared.global [%0], [%1], 16;" :: "r"(d), "l"(g));
        }
        asm volatile("cp.async.commit_group;" ::: "memory");
    };

    load_chunk(0, 0);

    for (int c = 0; c < 2; ++c) {
        if (c == 0) {
            load_chunk(1, 1);
            asm volatile("cp.async.wait_group 1;" ::: "memory");
        } else {
            asm volatile("cp.async.wait_group 0;" ::: "memory");
        }
        __syncthreads();

        const u32 sA = sbase + (c & 1) * 2 * TILE_B;
        const u32 sB = sA + TILE_B;
#pragma unroll
        for (int ks = 0; ks < 4; ++ks) {
            const u32 kb = ks << 4;
            u32 ah[4][4], bh[2][4];
#pragma unroll
            for (int mt = 0; mt < 4; ++mt)
                ldsm4(ah[mt], swz(sA, wm + mt * 16 + a_row, kb + a_k));
#pragma unroll
            for (int np = 0; np < 2; ++np)
                ldsm4(bh[np], swz(sB, wn + np * 16 + b_row, kb + b_k));
#pragma unroll
            for (int mt = 0; mt < 4; ++mt)
#pragma unroll
                for (int nt = 0; nt < 4; ++nt)
                    mma_f16(acc[mt][nt], ah[mt], &bh[nt >> 1][(nt & 1) * 2]);
        }
        __syncthreads();
    }

    const int g  = lane >> 2;
    const int tg = lane & 3;
    const float* cvz = cv + (size_t)z * NH;

#pragma unroll
    for (int nt = 0; nt < 4; ++nt) {
        const int cc = n0 + wn + nt * 8 + tg * 2;
        float2 cb = *(const float2*)(cvz + cc);
#pragma unroll
        for (int mt = 0; mt < 4; ++mt)
#pragma unroll
            for (int h = 0; h < 2; ++h) {
                acc[mt][nt][h * 2 + 0] += cb.x;
                acc[mt][nt][h * 2 + 1] += cb.y;
            }
    }

    // per-row tile max
#pragma unroll
    for (int mt = 0; mt < 4; ++mt)
#pragma unroll
        for (int h = 0; h < 2; ++h) {
            float mx = -1e30f;
#pragma unroll
            for (int nt = 0; nt < 4; ++nt)
                mx = fmaxf(mx, fmaxf(acc[mt][nt][h * 2], acc[mt][nt][h * 2 + 1]));
            mx = fmaxf(mx, __shfl_xor_sync(0xFFFFFFFFu, mx, 1));
            mx = fmaxf(mx, __shfl_xor_sync(0xFFFFFFFFu, mx, 2));
            if (tg == 0) wred[wcol][wm + mt * 16 + g + h * 8] = mx;
        }
    __syncthreads();
    if (tid < 128)
        mrow[tid] = fmaxf(fmaxf(wred[0][tid], wred[1][tid]),
                          fmaxf(wred[2][tid], wred[3][tid]));
    __syncthreads();

    __half* Pz = P + (size_t)z * NC * NH;
#pragma unroll
    for (int mt = 0; mt < 4; ++mt)
#pragma unroll
        for (int h = 0; h < 2; ++h) {
            const int lr = wm + mt * 16 + g + h * 8;
            const int r = m0 + lr;
            const float m = mrow[lr];
            float rowacc = 0.f;
#pragma unroll
            for (int nt = 0; nt < 4; ++nt) {
                const int cc = n0 + wn + nt * 8 + tg * 2;
                float e0 = __expf(acc[mt][nt][h * 2 + 0] - m);
                float e1 = __expf(acc[mt][nt][h * 2 + 1] - m);
                *(__half2*)(Pz + (size_t)r * NH + cc) =
                    __halves2half2(__float2half_rn(e0), __float2half_rn(e1));
                rowacc += e0 + e1;
            }
            rowacc += __shfl_xor_sync(0xFFFFFFFFu, rowacc, 1);
            rowacc += __shfl_xor_sync(0xFFFFFFFFu, rowacc, 2);
            if (tg == 0) wred[wcol][lr] = rowacc;
        }
    __syncthreads();
    if (tid < 128) {
        const size_t o = ((size_t)z * NTILE + blockIdx.x) * NC + m0 + tid;
        M[o]  = mrow[tid];
        Zp[o] = wred[0][tid] + wred[1][tid] + wred[2][tid] + wred[3][tid];
    }
}

// per-row global max + normalized per-tile factors F = exp(M-m)/Z. grid (NC/256, NL).
__global__ __launch_bounds__(256)
void sfix(const float* __restrict__ M, const float* __restrict__ Zp,
          float* __restrict__ F)
{
    const int z = blockIdx.y;
    const int r = blockIdx.x * 256 + threadIdx.x;
    float m = -1e30f;
    for (int t = 0; t < NTILE; ++t)
        m = fmaxf(m, M[((size_t)z * NTILE + t) * NC + r]);
    float zs = 0.f;
    for (int t = 0; t < NTILE; ++t) {
        const size_t o = ((size_t)z * NTILE + t) * NC + r;
        zs += Zp[o] * __expf(M[o] - m);
    }
    const float inv = 1.f / zs;
    for (int t = 0; t < NTILE; ++t) {
        const size_t o = ((size_t)z * NTILE + t) * NC + r;
        F[o] = __expf(M[o] - m) * inv;
    }
}

// ======================================================================
// Fused AV over all levels with factor folding, L2-optimal tile:
// out[r][n] = bf[n] + sum_z sum_t F[z][t][r] * (P_tile @ VfT_z^T)
// CTA 128x128, K flat over (z, chunks), 2-stage, 256 threads, 1 CTA/SM.
// Per 128-col tile (2 chunks): acc2 fresh-MMA, flush acc += acc2*F (F via LDG).
// ======================================================================
__global__ __launch_bounds__(256, 1)
void avz_k(const __half* __restrict__ P, const __half* __restrict__ VfT,
           const float* __restrict__ Fz, const float* __restrict__ bf,
           float* __restrict__ out)
{
    extern __shared__ __align__(1024) char smem[];
    const int tid  = threadIdx.x;
    const int wid  = tid >> 5;
    const int lane = tid & 31;
    const int n0 = blockIdx.x * 128;
    const int m0 = blockIdx.y * 128;
    const int wm = (wid & 1) * 64;
    const int wn = (wid >> 1) * 32;

    const u32 sbase = smem_u32(smem);

    float acc[4][4][4], acc2[4][4][4];
#pragma unroll
    for (int i = 0; i < 4; ++i)
#pragma unroll
        for (int j = 0; j < 4; ++j)
#pragma unroll
            for (int h = 0; h < 4; ++h) { acc[i][j][h] = 0.f; acc2[i][j][h] = 0.f; }

    const u32 a_row = lane & 15;
    const u32 a_k   = (lane >> 4) << 3;
    const u32 b_row = ((lane >> 4) << 3) + (lane & 7);
    const u32 b_k   = ((lane >> 3) & 1) << 3;

    auto load_chunk = [&](int cg) {
        const int z = cg >> 7;
        const int c = cg & 127;
        const int kb = c * KC;
        const u32 sb = sbase + (cg & 1) * AV_STAGE;
#pragma unroll
        for (int i = 0; i < 8; ++i) {        // 4 iters A tile + 4 iters B tile
            const int t  = i >> 2;           // 0 = A (P), 1 = B (VfT)
            const int cc = ((i & 3) << 8) + tid;   // 0..1023 chunks per tile
            const int row = cc >> 3;               // 0..127
            const int k8  = cc & 7;
            const __half* g = t
                ? (VfT + (size_t)z * FD * NH + (size_t)(n0 + row) * NH + kb + (k8 << 3))
                : (P   + (size_t)z * NC * NH + (size_t)(m0 + row) * NH + kb + (k8 << 3));
            const u32 d = sb + t * TILE_B + row * 128
                        + (((u32)k8 ^ ((u32)row & 7)) << 4);
            asm volatile("cp.async.cg.shared.global [%0], [%1], 16;" :: "r"(d), "l"(g));
        }
        asm volatile("cp.async.commit_group;" ::: "memory");
    };

    const int NCHG = NL * (NH / KC);   // 384
    load_chunk(0);

    const int g  = lane >> 2;
    const int tg = lane & 3;

    for (int cg = 0; cg < NCHG; ++cg) {
        if (cg + 1 < NCHG) {
            load_chunk(cg + 1);
            asm volatile("cp.async.wait_group 1;" ::: "memory");
        } else {
            asm volatile("cp.async.wait_group 0;" ::: "memory");
        }
        __syncthreads();

        const u32 sA = sbase + (cg & 1) * AV_STAGE;
        const u32 sB = sA + TILE_B;
        const bool fresh = ((cg & 1) == 0);
#pragma unroll
        for (int ks = 0; ks < 4; ++ks) {
            const u32 kb = ks << 4;
            u32 ah[4][4], bh[2][4];
#pragma unroll
            for (int mt = 0; mt < 4; ++mt)
                ldsm4(ah[mt], swz(sA, wm + mt * 16 + a_row, kb + a_k));
#pragma unroll
            for (int np = 0; np < 2; ++np)
                ldsm4(bh[np], swz(sB, wn + np * 16 + b_row, kb + b_k));
            if (ks == 0 && fresh) {
#pragma unroll
                for (int mt = 0; mt < 4; ++mt)
#pragma unroll
                    for (int nt = 0; nt < 4; ++nt)
                        mma_f16_zc(acc2[mt][nt], ah[mt], &bh[nt >> 1][(nt & 1) * 2]);
            } else {
#pragma unroll
                for (int mt = 0; mt < 4; ++mt)
#pragma unroll
                    for (int nt = 0; nt < 4; ++nt)
                        mma_f16(acc2[mt][nt], ah[mt], &bh[nt >> 1][(nt & 1) * 2]);
            }
        }
        __syncthreads();

        if (cg & 1) {   // flush 128-col tile: acc += acc2 * F[z][t][row]
            const int z = cg >> 7;
            const int t = (cg & 127) >> 1;
            const float* Ft = Fz + ((size_t)z * NTILE + t) * NC + m0;
#pragma unroll
            for (int mt = 0; mt < 4; ++mt)
#pragma unroll
                for (int h = 0; h < 2; ++h) {
                    const float f = Ft[wm + mt * 16 + g + h * 8];   // L2-resident
#pragma unroll
                    for (int nt = 0; nt < 4; ++nt) {
                        acc[mt][nt][h * 2 + 0] = fmaf(acc2[mt][nt][h * 2 + 0], f,
                                                      acc[mt][nt][h * 2 + 0]);
                        acc[mt][nt][h * 2 + 1] = fmaf(acc2[mt][nt][h * 2 + 1], f,
                                                      acc[mt][nt][h * 2 + 1]);
                    }
                }
        }
    }

#pragma unroll
    for (int mt = 0; mt < 4; ++mt)
#pragma unroll
        for (int nt = 0; nt < 4; ++nt) {
            const int cc = n0 + wn + nt * 8 + tg * 2;
            const float2 b = *(const float2*)(bf + cc);
#pragma unroll
            for (int h = 0; h < 2; ++h) {
                const int r = m0 + wm + mt * 16 + g + h * 8;
                *(float2*)(out + (size_t)r * FD + cc) =
                    make_float2(acc[mt][nt][h * 2 + 0] + b.x,
                                acc[mt][nt][h * 2 + 1] + b.y);
            }
        }
}

// ---------------- small kernels ----------------
__global__ __launch_bounds__(256)
void split_rm(const float* __restrict__ X,
              __nv_bfloat16* __restrict__ hi, __nv_bfloat16* __restrict__ lo)
{
    const size_t i = ((size_t)blockIdx.x * 256 + threadIdx.x) << 2;
    float4 v = *(const float4*)(X + i);
    __nv_bfloat16 h0 = __float2bfloat16(v.x), h1 = __float2bfloat16(v.y);
    __nv_bfloat16 h2 = __float2bfloat16(v.z), h3 = __float2bfloat16(v.w);
    *(__nv_bfloat162*)(hi + i)     = __halves2bfloat162(h0, h1);
    *(__nv_bfloat162*)(hi + i + 2) = __halves2bfloat162(h2, h3);
    *(__nv_bfloat162*)(lo + i)     = __halves2bfloat162(
        __float2bfloat16(v.x - __bfloat162float(h0)), __float2bfloat16(v.y - __bfloat162float(h1)));
    *(__nv_bfloat162*)(lo + i + 2) = __halves2bfloat162(
        __float2bfloat16(v.z - __bfloat162float(h2)), __float2bfloat16(v.w - __bfloat162float(h3)));
}

// hist: one read -> bf16 split + fp16 copy
__global__ __launch_bounds__(256)
void split_h3(const float* __restrict__ X,
              __nv_bfloat16* __restrict__ hi, __nv_bfloat16* __restrict__ lo,
              __half* __restrict__ f16)
{
    const size_t i = ((size_t)blockIdx.x * 256 + threadIdx.x) << 2;
    float4 v = *(const float4*)(X + i);
    __nv_bfloat16 h0 = __float2bfloat16(v.x), h1 = __float2bfloat16(v.y);
    __nv_bfloat16 h2 = __float2bfloat16(v.z), h3 = __float2bfloat16(v.w);
    *(__nv_bfloat162*)(hi + i)     = __halves2bfloat162(h0, h1);
    *(__nv_bfloat162*)(hi + i + 2) = __halves2bfloat162(h2, h3);
    *(__nv_bfloat162*)(lo + i)     = __halves2bfloat162(
        __float2bfloat16(v.x - __bfloat162float(h0)), __float2bfloat16(v.y - __bfloat162float(h1)));
    *(__nv_bfloat162*)(lo + i + 2) = __halves2bfloat162(
        __float2bfloat16(v.z - __bfloat162float(h2)), __float2bfloat16(v.w - __bfloat162float(h3)));
    *(__half2*)(f16 + i)     = __halves2half2(__float2half_rn(v.x), __float2half_rn(v.y));
    *(__half2*)(f16 + i + 2) = __halves2half2(__float2half_rn(v.z), __float2half_rn(v.w));
}

__global__ __launch_bounds__(256)
void cvt16(const float* __restrict__ X, __half* __restrict__ o)
{
    const size_t i = ((size_t)blockIdx.x * 256 + threadIdx.x) << 2;
    float4 v = *(const float4*)(X + i);
    *(__half2*)(o + i)     = __halves2half2(__float2half_rn(v.x), __float2half_rn(v.y));
    *(__half2*)(o + i + 2) = __halves2half2(__float2half_rn(v.z), __float2half_rn(v.w));
}

__global__ void gmat(const float* __restrict__ W2,
                     __nv_bfloat16* __restrict__ Ghi, __nv_bfloat16* __restrict__ Glo)
{
    const int i = blockIdx.x, l = blockIdx.y, j = threadIdx.x;
    const float* W = W2 + (size_t)l * FD * RD;
    float a = 0.f;
    for (int d = 0; d < FD; ++d) a += W[(size_t)d * RD + i] * W[(size_t)d * RD + j];
    a *= SCALE;
    __nv_bfloat16 h = __float2bfloat16(a);
    const size_t o = (size_t)l * RD * RD + (size_t)i * RD + j;
    Ghi[o] = h;
    Glo[o] = __float2bfloat16(a - __bfloat162float(h));
}

__global__ void vvec(const float* __restrict__ W2, const float* __restrict__ b2,
                     float* __restrict__ v)
{
    const int l = blockIdx.x, r = threadIdx.x;
    const float* W = W2 + (size_t)l * FD * RD;
    const float* b = b2 + (size_t)l * FD;
    float a = 0.f;
    for (int d = 0; d < FD; ++d) a += W[(size_t)d * RD + r] * b[d];
    v[l * RD + r] = a * SCALE;
}

__global__ __launch_bounds__(256)
void cvec_k(const __half* __restrict__ Hhf, const float* __restrict__ v,
            float* __restrict__ cv)
{
    const int z = blockIdx.y;
    const int m = blockIdx.x * 256 + threadIdx.x;
    const __half* h = Hhf + (size_t)z * NH * RD + (size_t)m * RD;
    const float* vz = v + z * RD;
    float a = 0.f;
#pragma unroll
    for (int r = 0; r < RD; r += 2) {
        __half2 p = *(const __half2*)(h + r);
        a += __low2float(p) * vz[r] + __high2float(p) * vz[r + 1];
    }
    cv[(size_t)z * NH + m] = a;
}

// ======================================================================
extern "C" void kernel_launch(void* const* d_in, const int* in_sizes, int n_in,
                              void* d_out, int out_size)
{
    const float* cur  = (const float*)d_in[0];
    const float* hist = (const float*)d_in[1];
    const float* W1   = (const float*)d_in[2];
    const float* b1   = (const float*)d_in[3];
    const float* W2   = (const float*)d_in[4];
    const float* b2   = (const float*)d_in[5];
    const float* Wf   = (const float*)d_in[6];
    const float* bf   = (const float*)d_in[7];
    float* out = (float*)d_out;

    __nv_bfloat16 *Xhi, *Xlo, *W1hi, *W1lo, *Ghi, *Glo, *Hhi, *Hlo;
    __half *Wf16, *X16, *Hhf, *Hcf, *P, *VfT;
    float *v, *cv, *M, *Zp, *F;
    cudaGetSymbolAddress((void**)&Xhi, g_Xhi);   cudaGetSymbolAddress((void**)&Xlo, g_Xlo);
    cudaGetSymbolAddress((void**)&W1hi, g_W1hi); cudaGetSymbolAddress((void**)&W1lo, g_W1lo);
    cudaGetSymbolAddress((void**)&Ghi, g_Ghi);   cudaGetSymbolAddress((void**)&Glo, g_Glo);
    cudaGetSymbolAddress((void**)&Hhi, g_Hhi);   cudaGetSymbolAddress((void**)&Hlo, g_Hlo);
    cudaGetSymbolAddress((void**)&Wf16, g_Wf16); cudaGetSymbolAddress((void**)&X16, g_X16);
    cudaGetSymbolAddress((void**)&Hhf, g_Hhf);   cudaGetSymbolAddress((void**)&Hcf, g_Hcf);
    cudaGetSymbolAddress((void**)&P, g_P);       cudaGetSymbolAddress((void**)&VfT, g_VfT);
    cudaGetSymbolAddress((void**)&v, g_v);       cudaGetSymbolAddress((void**)&cv, g_cv);
    cudaGetSymbolAddress((void**)&M, g_M);       cudaGetSymbolAddress((void**)&Zp, g_Zp);
    cudaGetSymbolAddress((void**)&F, g_F);

    cudaFuncSetAttribute(mm128b<true,  1>, cudaFuncAttributeMaxDynamicSharedMemorySize, GSMEM_B);
    cudaFuncSetAttribute(mm128b<false, 2>, cudaFuncAttributeMaxDynamicSharedMemorySize, GSMEM_B);
    cudaFuncSetAttribute(vft_k,  cudaFuncAttributeMaxDynamicSharedMemorySize, GSMEM_V);
    cudaFuncSetAttribute(sexp_k, cudaFuncAttributeMaxDynamicSharedMemorySize, GSMEM_SX);
    cudaFuncSetAttribute(avz_k,  cudaFuncAttributeMaxDynamicSharedMemorySize, GSMEM_AV);

    // ---- preprocessing (single stream) ----
    split_rm<<<(NC * FD) / 1024, 256>>>(cur, Xhi, Xlo);
    split_h3<<<(NH * FD) / 1024, 256>>>(hist, Xhi + (size_t)NC * FD, Xlo + (size_t)NC * FD, X16);
    split_rm<<<(NL * RD * FD) / 1024, 256>>>(W1, W1hi, W1lo);
    cvt16<<<(FD * NL * FD) / 1024, 256>>>(Wf, Wf16);
    gmat<<<dim3(RD, NL), RD>>>(W2, Ghi, Glo);
    vvec<<<NL, RD>>>(W2, b2, v);

    // VfT_l = Wf_l @ hist^T  [FD, NH] fp16-1
    vft_k<<<dim3(NH / 128, FD / 128, NL), 256, GSMEM_V>>>(Wf16, X16, VfT);

    // H_l = relu(X @ W1_l^T + b1_l): split (rows<NC) + fp16 (rows>=NC)
    mm128b<true, 1><<<dim3(RD / 128, NT / 128, NL), 256, GSMEM_B>>>(
        Xhi, Xlo, 0, FD,
        W1hi, W1lo, (size_t)RD * FD, FD,
        b1, (size_t)RD,
        Hhi, Hlo, (size_t)NT * RD, RD,
        Hhf, (size_t)NH * RD, RD, FD);

    // cv[z] = Hhf[z] . v[z]
    cvec_k<<<dim3(NH / 256, NL), 256>>>(Hhf, v, cv);

    // Hc'_l = Hc_l @ G_l (pre-scaled)  [NC, RD] fp16
    mm128b<false, 2><<<dim3(RD / 128, NC / 128, NL), 256, GSMEM_B>>>(
        Hhi, Hlo, (size_t)NT * RD, RD,
        Ghi, Glo, (size_t)RD * RD, RD,
        nullptr, 0,
        nullptr, nullptr, 0, 0,
        Hcf, (size_t)NC * RD, RD, RD);

    // P = exp(s - m_tile); M, Zp partials
    sexp_k<<<dim3(NH / 128, NC / 128, NL), 256, GSMEM_SX>>>(Hcf, Hhf, cv, P, M, Zp);

    // normalized per-tile factors F = exp(M - m) / Z
    sfix<<<dim3(NC / 256, NL), 256>>>(M, Zp, F);

    // out = bf + sum_z sum_t F * (P_tile @ VfT^T)
    avz_k<<<dim3(FD / 128, NC / 128), 256, GSMEM_AV>>>(P, VfT, F, bf, out);
}

// round 15
// speedup vs baseline: 1.5566x; 1.5566x over previous
#include <cuda_runtime.h>
#include <cuda_bf16.h>
#include <cuda_fp16.h>

#define NC 4096
#define NH 8192
#define NT 12288
#define FD 512
#define RD 128
#define NL 3
#define NTILE (NH / 128)          // 64 S-tiles per row

typedef unsigned long long u64;
typedef unsigned int u32;

#define KC 64                     // k elements per chunk
#define TILE_B 16384              // 128 rows x 64 elems x 2B
#define GSMEM_B (2 * 4 * TILE_B)  // bf16-3 kernel: 2 stages x 4 tiles = 128KB
#define GSMEM_SX (2 * 2 * TILE_B) // sexp: 2 stages x (A,B) = 64KB
#define GSMEM_V  (3 * 2 * TILE_B) // vft: 3 stages x (A,B) = 96KB

// AV kernel tiling: BM=64, BN=128
// traffic = P*(FD/128) + VfT*(NC/64) = 804MB + 1.6GB = 2.4GB; acc regs = 64 (no spill)
#define AV_BM 64
#define AV_TA (AV_BM * 128)            // 8KB
#define AV_STAGE (AV_TA + TILE_B)      // 24KB
#define GSMEM_AV (2 * AV_STAGE)        // 48KB -> 2 CTAs/SM

static const float SCALE = 0.044194173824159216f;  // 1/sqrt(512)

// ---------------- helpers ----------------
__device__ __forceinline__ u32 smem_u32(const void* p) {
    u32 a;
    asm("{ .reg .u64 t; cvta.to.shared.u64 t, %1; cvt.u32.u64 %0, t; }" : "=r"(a) : "l"(p));
    return a;
}
__device__ __forceinline__ void ldsm4(u32* r, u32 addr) {
    asm volatile("ldmatrix.sync.aligned.m8n8.x4.shared.b16 {%0,%1,%2,%3}, [%4];"
                 : "=r"(r[0]), "=r"(r[1]), "=r"(r[2]), "=r"(r[3]) : "r"(addr));
}
__device__ __forceinline__ void mma_bf16(float* c, const u32* a, const u32* b) {
    asm volatile("mma.sync.aligned.m16n8k16.row.col.f32.bf16.bf16.f32 "
                 "{%0,%1,%2,%3}, {%4,%5,%6,%7}, {%8,%9}, {%0,%1,%2,%3};"
                 : "+f"(c[0]), "+f"(c[1]), "+f"(c[2]), "+f"(c[3])
                 : "r"(a[0]), "r"(a[1]), "r"(a[2]), "r"(a[3]), "r"(b[0]), "r"(b[1]));
}
__device__ __forceinline__ void mma_f16(float* c, const u32* a, const u32* b) {
    asm volatile("mma.sync.aligned.m16n8k16.row.col.f32.f16.f16.f32 "
                 "{%0,%1,%2,%3}, {%4,%5,%6,%7}, {%8,%9}, {%0,%1,%2,%3};"
                 : "+f"(c[0]), "+f"(c[1]), "+f"(c[2]), "+f"(c[3])
                 : "r"(a[0]), "r"(a[1]), "r"(a[2]), "r"(a[3]), "r"(b[0]), "r"(b[1]));
}
// D = A*B + 0  (fresh accumulator: avoids explicit acc2 zeroing)
__device__ __forceinline__ void mma_f16_zc(float* c, const u32* a, const u32* b) {
    asm volatile("mma.sync.aligned.m16n8k16.row.col.f32.f16.f16.f32 "
                 "{%0,%1,%2,%3}, {%4,%5,%6,%7}, {%8,%9}, {%10,%11,%12,%13};"
                 : "=f"(c[0]), "=f"(c[1]), "=f"(c[2]), "=f"(c[3])
                 : "r"(a[0]), "r"(a[1]), "r"(a[2]), "r"(a[3]), "r"(b[0]), "r"(b[1]),
                   "f"(0.f), "f"(0.f), "f"(0.f), "f"(0.f));
}
__device__ __forceinline__ u32 swz(u32 base, u32 row, u32 k) {
    return base + row * 128 + ((((k >> 3) ^ (row & 7)) & 7) << 4);
}

// ---------------- scratch ----------------
__device__ __align__(128) __nv_bfloat16 g_Xhi[(size_t)NT * FD],  g_Xlo[(size_t)NT * FD];
__device__ __align__(128) __nv_bfloat16 g_W1hi[(size_t)NL * RD * FD], g_W1lo[(size_t)NL * RD * FD];
__device__ __align__(128) __nv_bfloat16 g_Ghi[(size_t)NL * RD * RD],  g_Glo[(size_t)NL * RD * RD];
__device__ __align__(128) __nv_bfloat16 g_Hhi[(size_t)NL * NT * RD],  g_Hlo[(size_t)NL * NT * RD];
__device__ __align__(128) __half        g_Wf16[(size_t)FD * NL * FD]; // Wf fp16
__device__ __align__(128) __half        g_X16 [(size_t)NH * FD];      // hist fp16
__device__ __align__(128) __half        g_Hhf[(size_t)NL * NH * RD];  // historical H, fp16
__device__ __align__(128) __half        g_Hcf[(size_t)NL * NC * RD];  // Hc*G*scale, fp16
__device__ __align__(128) __half        g_P  [(size_t)NL * NC * NH];  // exp(s - m_tile) per tile
__device__ __align__(128) float         g_M  [(size_t)NL * NTILE * NC];  // per-tile row max
__device__ __align__(128) float         g_Zp [(size_t)NL * NTILE * NC];  // per-tile row sums
__device__ __align__(128) float         g_F  [(size_t)NL * NTILE * NC];  // exp(M - m_row) / Z
__device__ __align__(128) __half        g_VfT[(size_t)NL * FD * NH];  // Wf_l @ hist^T
__device__ __align__(128) float         g_v  [NL * RD];
__device__ __align__(128) float         g_cv [NL * NH];

// ======================================================================
// Split-bf16 HMMA GEMM (3 products), z-batched: C = act(A@B^T + bias)
// OM 1: split out (rows<NC) + fp16 out (rows>=NC)   OM 2: fp16 out
// ======================================================================
template<bool RELU, int OM>
__global__ __launch_bounds__(256, 1)
void mm128b(const __nv_bfloat16* __restrict__ Ahi, const __nv_bfloat16* __restrict__ Alo,
            size_t zsA, int lda,
            const __nv_bfloat16* __restrict__ Bhi, const __nv_bfloat16* __restrict__ Blo,
            size_t zsB, int ldb,
            const float* __restrict__ bias, size_t zsBias,
            __nv_bfloat16* __restrict__ Chi, __nv_bfloat16* __restrict__ Clo,
            size_t zsC, int ldcs,
            __half* __restrict__ Ch, size_t zsCh, int ldch,
            int K)
{
    extern __shared__ __align__(1024) char smem[];
    const int tid  = threadIdx.x;
    const int wid  = tid >> 5;
    const int lane = tid & 31;
    const int z  = blockIdx.z;
    const int m0 = blockIdx.y * 128;
    const int n0 = blockIdx.x * 128;
    const int wm = (wid & 1) * 64;
    const int wn = (wid >> 1) * 32;

    const u32 sbase = smem_u32(smem);
    const __nv_bfloat16* srcs[4] = {
        Ahi + zsA * z + (size_t)m0 * lda, Alo + zsA * z + (size_t)m0 * lda,
        Bhi + zsB * z + (size_t)n0 * ldb, Blo + zsB * z + (size_t)n0 * ldb };
    const int lds[4] = { lda, lda, ldb, ldb };

    float acc[4][4][4];
#pragma unroll
    for (int i = 0; i < 4; ++i)
#pragma unroll
        for (int j = 0; j < 4; ++j)
#pragma unroll
            for (int h = 0; h < 4; ++h) acc[i][j][h] = 0.f;

    const u32 a_row = lane & 15;
    const u32 a_k   = (lane >> 4) << 3;
    const u32 b_row = ((lane >> 4) << 3) + (lane & 7);
    const u32 b_k   = ((lane >> 3) & 1) << 3;

    const int nch = K / KC;

    auto load_chunk = [&](int c, int buf) {
        const int kb = c * KC;
        const u32 sb = sbase + buf * 4 * TILE_B;
#pragma unroll
        for (int i = 0; i < 16; ++i) {
            const int t  = i >> 2;
            const int cc = ((i & 3) << 8) + tid;
            const int row = cc >> 3;
            const int k8  = cc & 7;
            const __nv_bfloat16* g = srcs[t] + (size_t)row * lds[t] + kb + (k8 << 3);
            const u32 d = sb + t * TILE_B + row * 128 + (((u32)k8 ^ ((u32)row & 7)) << 4);
            asm volatile("cp.async.cg.shared.global [%0], [%1], 16;" :: "r"(d), "l"(g));
        }
        asm volatile("cp.async.commit_group;" ::: "memory");
    };

    load_chunk(0, 0);

    for (int c = 0; c < nch; ++c) {
        if (c + 1 < nch) {
            load_chunk(c + 1, (c + 1) & 1);
            asm volatile("cp.async.wait_group 1;" ::: "memory");
        } else {
            asm volatile("cp.async.wait_group 0;" ::: "memory");
        }
        __syncthreads();

        const u32 sA_h = sbase + (c & 1) * 4 * TILE_B;
        const u32 sA_l = sA_h + TILE_B;
        const u32 sB_h = sA_h + 2 * TILE_B;
        const u32 sB_l = sA_h + 3 * TILE_B;

#pragma unroll
        for (int ks = 0; ks < 4; ++ks) {
            const u32 kb = ks << 4;
            u32 ah[4][4], al[4][4], bh[2][4], bl[2][4];
#pragma unroll
            for (int mt = 0; mt < 4; ++mt) {
                ldsm4(ah[mt], swz(sA_h, wm + mt * 16 + a_row, kb + a_k));
                ldsm4(al[mt], swz(sA_l, wm + mt * 16 + a_row, kb + a_k));
            }
#pragma unroll
            for (int np = 0; np < 2; ++np) {
                ldsm4(bh[np], swz(sB_h, wn + np * 16 + b_row, kb + b_k));
                ldsm4(bl[np], swz(sB_l, wn + np * 16 + b_row, kb + b_k));
            }
#pragma unroll
            for (int mt = 0; mt < 4; ++mt)
#pragma unroll
                for (int nt = 0; nt < 4; ++nt) {
                    const u32* bhp = &bh[nt >> 1][(nt & 1) * 2];
                    const u32* blp = &bl[nt >> 1][(nt & 1) * 2];
                    mma_bf16(acc[mt][nt], ah[mt], bhp);
                    mma_bf16(acc[mt][nt], ah[mt], blp);
                    mma_bf16(acc[mt][nt], al[mt], bhp);
                }
        }
        __syncthreads();
    }

    const int g  = lane >> 2;
    const int tg = lane & 3;
#pragma unroll
    for (int mt = 0; mt < 4; ++mt)
#pragma unroll
        for (int nt = 0; nt < 4; ++nt) {
            const int cc = n0 + wn + nt * 8 + tg * 2;
#pragma unroll
            for (int h = 0; h < 2; ++h) {
                const int r = m0 + wm + mt * 16 + g + h * 8;
                float v0 = acc[mt][nt][h * 2 + 0];
                float v1 = acc[mt][nt][h * 2 + 1];
                if (bias) { v0 += bias[zsBias * z + cc]; v1 += bias[zsBias * z + cc + 1]; }
                if (RELU) { v0 = fmaxf(v0, 0.f); v1 = fmaxf(v1, 0.f); }
                if (OM == 1) {
                    if (r < NC) {
                        __nv_bfloat16 h0 = __float2bfloat16(v0);
                        __nv_bfloat16 h1 = __float2bfloat16(v1);
                        *(__nv_bfloat162*)(Chi + zsC * z + (size_t)r * ldcs + cc) =
                            __halves2bfloat162(h0, h1);
                        *(__nv_bfloat162*)(Clo + zsC * z + (size_t)r * ldcs + cc) =
                            __halves2bfloat162(
                                __float2bfloat16(v0 - __bfloat162float(h0)),
                                __float2bfloat16(v1 - __bfloat162float(h1)));
                    } else {
                        *(__half2*)(Ch + zsCh * z + (size_t)(r - NC) * ldch + cc) =
                            __halves2half2(__float2half_rn(v0), __float2half_rn(v1));
                    }
                }
                if (OM == 2)
                    *(__half2*)(Ch + zsCh * z + (size_t)r * ldch + cc) =
                        __halves2half2(__float2half_rn(v0), __float2half_rn(v1));
            }
        }
}

// ======================================================================
// fp16 single-product GEMM for VfT: C[FD,NH] = Wf_l @ hist^T, fp16 out.
// ======================================================================
__global__ __launch_bounds__(256, 2)
void vft_k(const __half* __restrict__ A, const __half* __restrict__ B,
           __half* __restrict__ C)
{
    extern __shared__ __align__(1024) char smem[];
    const int tid  = threadIdx.x;
    const int wid  = tid >> 5;
    const int lane = tid & 31;
    const int z  = blockIdx.z;
    const int m0 = blockIdx.y * 128;     // FD rows
    const int n0 = blockIdx.x * 128;     // NH rows
    const int wm = (wid & 1) * 64;
    const int wn = (wid >> 1) * 32;

    const u32 sbase = smem_u32(smem);
    const __half* Asrc = A + (size_t)z * FD + (size_t)m0 * (NL * FD);  // lda = NL*FD
    const __half* Bsrc = B + (size_t)n0 * FD;                          // ldb = FD

    float acc[4][4][4];
#pragma unroll
    for (int i = 0; i < 4; ++i)
#pragma unroll
        for (int j = 0; j < 4; ++j)
#pragma unroll
            for (int h = 0; h < 4; ++h) acc[i][j][h] = 0.f;

    const u32 a_row = lane & 15;
    const u32 a_k   = (lane >> 4) << 3;
    const u32 b_row = ((lane >> 4) << 3) + (lane & 7);
    const u32 b_k   = ((lane >> 3) & 1) << 3;

    const int nch = FD / KC;   // 8

    auto load_chunk = [&](int c) {
        const int kb = c * KC;
        const u32 sb = sbase + (c % 3) * 2 * TILE_B;
#pragma unroll
        for (int i = 0; i < 8; ++i) {
            const int t  = i >> 2;
            const int cc = ((i & 3) << 8) + tid;
            const int row = cc >> 3;
            const int k8  = cc & 7;
            const __half* g = (t ? (Bsrc + (size_t)row * FD) : (Asrc + (size_t)row * (NL * FD)))
                              + kb + (k8 << 3);
            const u32 d = sb + t * TILE_B + row * 128 + (((u32)k8 ^ ((u32)row & 7)) << 4);
            asm volatile("cp.async.cg.shared.global [%0], [%1], 16;" :: "r"(d), "l"(g));
        }
        asm volatile("cp.async.commit_group;" ::: "memory");
    };

    load_chunk(0);
    load_chunk(1);

    for (int c = 0; c < nch; ++c) {
        if (c + 1 < nch) { asm volatile("cp.async.wait_group 1;" ::: "memory"); }
        else             { asm volatile("cp.async.wait_group 0;" ::: "memory"); }
        __syncthreads();
        if (c + 2 < nch) load_chunk(c + 2);

        const u32 sA = sbase + (c % 3) * 2 * TILE_B;
        const u32 sB = sA + TILE_B;
#pragma unroll
        for (int ks = 0; ks < 4; ++ks) {
            const u32 kb = ks << 4;
            u32 ah[4][4], bh[2][4];
#pragma unroll
            for (int mt = 0; mt < 4; ++mt)
                ldsm4(ah[mt], swz(sA, wm + mt * 16 + a_row, kb + a_k));
#pragma unroll
            for (int np = 0; np < 2; ++np)
                ldsm4(bh[np], swz(sB, wn + np * 16 + b_row, kb + b_k));
#pragma unroll
            for (int mt = 0; mt < 4; ++mt)
#pragma unroll
                for (int nt = 0; nt < 4; ++nt)
                    mma_f16(acc[mt][nt], ah[mt], &bh[nt >> 1][(nt & 1) * 2]);
        }
    }

    const int g  = lane >> 2;
    const int tg = lane & 3;
    __half* Cz = C + (size_t)z * FD * NH;
#pragma unroll
    for (int mt = 0; mt < 4; ++mt)
#pragma unroll
        for (int nt = 0; nt < 4; ++nt) {
            const int cc = n0 + wn + nt * 8 + tg * 2;
#pragma unroll
            for (int h = 0; h < 2; ++h) {
                const int r = m0 + wm + mt * 16 + g + h * 8;
                *(__half2*)(Cz + (size_t)r * NH + cc) =
                    __halves2half2(__float2half_rn(acc[mt][nt][h * 2 + 0]),
                                   __float2half_rn(acc[mt][nt][h * 2 + 1]));
            }
        }
}

// ======================================================================
// S+exp with per-tile row max (flash-style, overflow-proof):
// P_tile = exp(s - m_tile) fp16; M, Zp per (z, tile, row), no atomics.
// ======================================================================
__global__ __launch_bounds__(256, 2)
void sexp_k(const __half* __restrict__ Hcf, const __half* __restrict__ Hhf,
            const float* __restrict__ cv,
            __half* __restrict__ P, float* __restrict__ M, float* __restrict__ Zp)
{
    extern __shared__ __align__(1024) char smem[];
    __shared__ float wred[4][128];
    __shared__ float mrow[128];
    const int tid  = threadIdx.x;
    const int wid  = tid >> 5;
    const int lane = tid & 31;
    const int z  = blockIdx.z;
    const int m0 = blockIdx.y * 128;
    const int n0 = blockIdx.x * 128;
    const int wm = (wid & 1) * 64;
    const int wn = (wid >> 1) * 32;
    const int wcol = wid >> 1;

    const u32 sbase = smem_u32(smem);
    const __half* Asrc = Hcf + (size_t)z * NC * RD + (size_t)m0 * RD;
    const __half* Bsrc = Hhf + (size_t)z * NH * RD + (size_t)n0 * RD;

    float acc[4][4][4];
#pragma unroll
    for (int i = 0; i < 4; ++i)
#pragma unroll
        for (int j = 0; j < 4; ++j)
#pragma unroll
            for (int h = 0; h < 4; ++h) acc[i][j][h] = 0.f;

    const u32 a_row = lane & 15;
    const u32 a_k   = (lane >> 4) << 3;
    const u32 b_row = ((lane >> 4) << 3) + (lane & 7);
    const u32 b_k   = ((lane >> 3) & 1) << 3;

    auto load_chunk = [&](int c, int buf) {
        const int kb = c * KC;
        const u32 sb = sbase + buf * 2 * TILE_B;
#pragma unroll
        for (int i = 0; i < 8; ++i) {
            const int t  = i >> 2;
            const int cc = ((i & 3) << 8) + tid;
            const int row = cc >> 3;
            const int k8  = cc & 7;
            const __half* g = (t ? Bsrc : Asrc) + (size_t)row * RD + kb + (k8 << 3);
            const u32 d = sb + t * TILE_B + row * 128 + (((u32)k8 ^ ((u32)row & 7)) << 4);
            asm volatile("cp.async.cg.shared.global [%0], [%1], 16;" :: "r"(d), "l"(g));
        }
        asm volatile("cp.async.commit_group;" ::: "memory");
    };

    load_chunk(0, 0);

    for (int c = 0; c < 2; ++c) {
        if (c == 0) {
            load_chunk(1, 1);
            asm volatile("cp.async.wait_group 1;" ::: "memory");
        } else {
            asm volatile("cp.async.wait_group 0;" ::: "memory");
        }
        __syncthreads();

        const u32 sA = sbase + (c & 1) * 2 * TILE_B;
        const u32 sB = sA + TILE_B;
#pragma unroll
        for (int ks = 0; ks < 4; ++ks) {
            const u32 kb = ks << 4;
            u32 ah[4][4], bh[2][4];
#pragma unroll
            for (int mt = 0; mt < 4; ++mt)
                ldsm4(ah[mt], swz(sA, wm + mt * 16 + a_row, kb + a_k));
#pragma unroll
            for (int np = 0; np < 2; ++np)
                ldsm4(bh[np], swz(sB, wn + np * 16 + b_row, kb + b_k));
#pragma unroll
            for (int mt = 0; mt < 4; ++mt)
#pragma unroll
                for (int nt = 0; nt < 4; ++nt)
                    mma_f16(acc[mt][nt], ah[mt], &bh[nt >> 1][(nt & 1) * 2]);
        }
        __syncthreads();
    }

    const int g  = lane >> 2;
    const int tg = lane & 3;
    const float* cvz = cv + (size_t)z * NH;

#pragma unroll
    for (int nt = 0; nt < 4; ++nt) {
        const int cc = n0 + wn + nt * 8 + tg * 2;
        float2 cb = *(const float2*)(cvz + cc);
#pragma unroll
        for (int mt = 0; mt < 4; ++mt)
#pragma unroll
            for (int h = 0; h < 2; ++h) {
                acc[mt][nt][h * 2 + 0] += cb.x;
                acc[mt][nt][h * 2 + 1] += cb.y;
            }
    }

    // per-row tile max
#pragma unroll
    for (int mt = 0; mt < 4; ++mt)
#pragma unroll
        for (int h = 0; h < 2; ++h) {
            float mx = -1e30f;
#pragma unroll
            for (int nt = 0; nt < 4; ++nt)
                mx = fmaxf(mx, fmaxf(acc[mt][nt][h * 2], acc[mt][nt][h * 2 + 1]));
            mx = fmaxf(mx, __shfl_xor_sync(0xFFFFFFFFu, mx, 1));
            mx = fmaxf(mx, __shfl_xor_sync(0xFFFFFFFFu, mx, 2));
            if (tg == 0) wred[wcol][wm + mt * 16 + g + h * 8] = mx;
        }
    __syncthreads();
    if (tid < 128)
        mrow[tid] = fmaxf(fmaxf(wred[0][tid], wred[1][tid]),
                          fmaxf(wred[2][tid], wred[3][tid]));
    __syncthreads();

    __half* Pz = P + (size_t)z * NC * NH;
#pragma unroll
    for (int mt = 0; mt < 4; ++mt)
#pragma unroll
        for (int h = 0; h < 2; ++h) {
            const int lr = wm + mt * 16 + g + h * 8;
            const int r = m0 + lr;
            const float m = mrow[lr];
            float rowacc = 0.f;
#pragma unroll
            for (int nt = 0; nt < 4; ++nt) {
                const int cc = n0 + wn + nt * 8 + tg * 2;
                float e0 = __expf(acc[mt][nt][h * 2 + 0] - m);
                float e1 = __expf(acc[mt][nt][h * 2 + 1] - m);
                *(__half2*)(Pz + (size_t)r * NH + cc) =
                    __halves2half2(__float2half_rn(e0), __float2half_rn(e1));
                rowacc += e0 + e1;
            }
            rowacc += __shfl_xor_sync(0xFFFFFFFFu, rowacc, 1);
            rowacc += __shfl_xor_sync(0xFFFFFFFFu, rowacc, 2);
            if (tg == 0) wred[wcol][lr] = rowacc;
        }
    __syncthreads();
    if (tid < 128) {
        const size_t o = ((size_t)z * NTILE + blockIdx.x) * NC + m0 + tid;
        M[o]  = mrow[tid];
        Zp[o] = wred[0][tid] + wred[1][tid] + wred[2][tid] + wred[3][tid];
    }
}

// per-row global max + normalized per-tile factors F = exp(M-m)/Z. grid (NC/256, NL).
__global__ __launch_bounds__(256)
void sfix(const float* __restrict__ M, const float* __restrict__ Zp,
          float* __restrict__ F)
{
    const int z = blockIdx.y;
    const int r = blockIdx.x * 256 + threadIdx.x;
    float m = -1e30f;
    for (int t = 0; t < NTILE; ++t)
        m = fmaxf(m, M[((size_t)z * NTILE + t) * NC + r]);
    float zs = 0.f;
    for (int t = 0; t < NTILE; ++t) {
        const size_t o = ((size_t)z * NTILE + t) * NC + r;
        zs += Zp[o] * __expf(M[o] - m);
    }
    const float inv = 1.f / zs;
    for (int t = 0; t < NTILE; ++t) {
        const size_t o = ((size_t)z * NTILE + t) * NC + r;
        F[o] = __expf(M[o] - m) * inv;
    }
}

// ======================================================================
// Fused AV over all levels with factor folding, BM=64 x BN=128:
// out[r][n] = bf[n] + sum_z sum_t F[z][t][r] * (P_tile @ VfT_z^T)
// 2-stage, 256 threads, 2 CTAs/SM; acc+acc2 = 64 regs (no spill).
// ======================================================================
__global__ __launch_bounds__(256, 2)
void avz_k(const __half* __restrict__ P, const __half* __restrict__ VfT,
           const float* __restrict__ Fz, const float* __restrict__ bf,
           float* __restrict__ out)
{
    extern __shared__ __align__(1024) char smem[];
    const int tid  = threadIdx.x;
    const int wid  = tid >> 5;
    const int lane = tid & 31;
    const int n0 = blockIdx.x * 128;
    const int m0 = blockIdx.y * AV_BM;
    const int wm = (wid & 1) * 32;       // mt < 2
    const int wn = (wid >> 1) * 32;      // nt < 4

    const u32 sbase = smem_u32(smem);

    float acc[2][4][4], acc2[2][4][4];
#pragma unroll
    for (int i = 0; i < 2; ++i)
#pragma unroll
        for (int j = 0; j < 4; ++j)
#pragma unroll
            for (int h = 0; h < 4; ++h) { acc[i][j][h] = 0.f; acc2[i][j][h] = 0.f; }

    const u32 a_row = lane & 15;
    const u32 a_k   = (lane >> 4) << 3;
    const u32 b_row = ((lane >> 4) << 3) + (lane & 7);
    const u32 b_k   = ((lane >> 3) & 1) << 3;

    auto load_chunk = [&](int cg) {
        const int z = cg >> 7;
        const int c = cg & 127;
        const int kb = c * KC;
        const u32 sb = sbase + (cg & 1) * AV_STAGE;
#pragma unroll
        for (int i = 0; i < 6; ++i) {        // 2 iters A (64 rows) + 4 iters B (128 rows)
            const bool isA = i < 2;
            const int cc = ((isA ? i : i - 2) << 8) + tid;
            const int row = cc >> 3;
            const int k8  = cc & 7;
            const __half* g = isA
                ? (P   + (size_t)z * NC * NH + (size_t)(m0 + row) * NH + kb + (k8 << 3))
                : (VfT + (size_t)z * FD * NH + (size_t)(n0 + row) * NH + kb + (k8 << 3));
            const u32 d = sb + (isA ? 0 : AV_TA) + row * 128
                        + (((u32)k8 ^ ((u32)row & 7)) << 4);
            asm volatile("cp.async.cg.shared.global [%0], [%1], 16;" :: "r"(d), "l"(g));
        }
        asm volatile("cp.async.commit_group;" ::: "memory");
    };

    const int NCHG = NL * (NH / KC);   // 384
    load_chunk(0);

    const int g  = lane >> 2;
    const int tg = lane & 3;

    for (int cg = 0; cg < NCHG; ++cg) {
        if (cg + 1 < NCHG) {
            load_chunk(cg + 1);
            asm volatile("cp.async.wait_group 1;" ::: "memory");
        } else {
            asm volatile("cp.async.wait_group 0;" ::: "memory");
        }
        __syncthreads();

        const u32 sA = sbase + (cg & 1) * AV_STAGE;
        const u32 sB = sA + AV_TA;
        const bool fresh = ((cg & 1) == 0);
#pragma unroll
        for (int ks = 0; ks < 4; ++ks) {
            const u32 kb = ks << 4;
            u32 ah[2][4], bh[2][4];
#pragma unroll
            for (int mt = 0; mt < 2; ++mt)
                ldsm4(ah[mt], swz(sA, wm + mt * 16 + a_row, kb + a_k));
#pragma unroll
            for (int np = 0; np < 2; ++np)
                ldsm4(bh[np], swz(sB, wn + np * 16 + b_row, kb + b_k));
            if (ks == 0 && fresh) {
#pragma unroll
                for (int mt = 0; mt < 2; ++mt)
#pragma unroll
                    for (int nt = 0; nt < 4; ++nt)
                        mma_f16_zc(acc2[mt][nt], ah[mt], &bh[nt >> 1][(nt & 1) * 2]);
            } else {
#pragma unroll
                for (int mt = 0; mt < 2; ++mt)
#pragma unroll
                    for (int nt = 0; nt < 4; ++nt)
                        mma_f16(acc2[mt][nt], ah[mt], &bh[nt >> 1][(nt & 1) * 2]);
            }
        }
        __syncthreads();

        if (cg & 1) {   // flush 128-col tile: acc += acc2 * F[z][t][row]
            const int z = cg >> 7;
            const int t = (cg & 127) >> 1;
            const float* Ft = Fz + ((size_t)z * NTILE + t) * NC + m0;
#pragma unroll
            for (int mt = 0; mt < 2; ++mt)
#pragma unroll
                for (int h = 0; h < 2; ++h) {
                    const float f = Ft[wm + mt * 16 + g + h * 8];   // L2-resident
#pragma unroll
                    for (int nt = 0; nt < 4; ++nt) {
                        acc[mt][nt][h * 2 + 0] = fmaf(acc2[mt][nt][h * 2 + 0], f,
                                                      acc[mt][nt][h * 2 + 0]);
                        acc[mt][nt][h * 2 + 1] = fmaf(acc2[mt][nt][h * 2 + 1], f,
                                                      acc[mt][nt][h * 2 + 1]);
                    }
                }
        }
    }

#pragma unroll
    for (int mt = 0; mt < 2; ++mt)
#pragma unroll
        for (int nt = 0; nt < 4; ++nt) {
            const int cc = n0 + wn + nt * 8 + tg * 2;
            const float2 b = *(const float2*)(bf + cc);
#pragma unroll
            for (int h = 0; h < 2; ++h) {
                const int r = m0 + wm + mt * 16 + g + h * 8;
                *(float2*)(out + (size_t)r * FD + cc) =
                    make_float2(acc[mt][nt][h * 2 + 0] + b.x,
                                acc[mt][nt][h * 2 + 1] + b.y);
            }
        }
}

// ---------------- small kernels ----------------
__global__ __launch_bounds__(256)
void split_rm(const float* __restrict__ X,
              __nv_bfloat16* __restrict__ hi, __nv_bfloat16* __restrict__ lo)
{
    const size_t i = ((size_t)blockIdx.x * 256 + threadIdx.x) << 2;
    float4 v = *(const float4*)(X + i);
    __nv_bfloat16 h0 = __float2bfloat16(v.x), h1 = __float2bfloat16(v.y);
    __nv_bfloat16 h2 = __float2bfloat16(v.z), h3 = __float2bfloat16(v.w);
    *(__nv_bfloat162*)(hi + i)     = __halves2bfloat162(h0, h1);
    *(__nv_bfloat162*)(hi + i + 2) = __halves2bfloat162(h2, h3);
    *(__nv_bfloat162*)(lo + i)     = __halves2bfloat162(
        __float2bfloat16(v.x - __bfloat162float(h0)), __float2bfloat16(v.y - __bfloat162float(h1)));
    *(__nv_bfloat162*)(lo + i + 2) = __halves2bfloat162(
        __float2bfloat16(v.z - __bfloat162float(h2)), __float2bfloat16(v.w - __bfloat162float(h3)));
}

// hist: one read -> bf16 split + fp16 copy
__global__ __launch_bounds__(256)
void split_h3(const float* __restrict__ X,
              __nv_bfloat16* __restrict__ hi, __nv_bfloat16* __restrict__ lo,
              __half* __restrict__ f16)
{
    const size_t i = ((size_t)blockIdx.x * 256 + threadIdx.x) << 2;
    float4 v = *(const float4*)(X + i);
    __nv_bfloat16 h0 = __float2bfloat16(v.x), h1 = __float2bfloat16(v.y);
    __nv_bfloat16 h2 = __float2bfloat16(v.z), h3 = __float2bfloat16(v.w);
    *(__nv_bfloat162*)(hi + i)     = __halves2bfloat162(h0, h1);
    *(__nv_bfloat162*)(hi + i + 2) = __halves2bfloat162(h2, h3);
    *(__nv_bfloat162*)(lo + i)     = __halves2bfloat162(
        __float2bfloat16(v.x - __bfloat162float(h0)), __float2bfloat16(v.y - __bfloat162float(h1)));
    *(__nv_bfloat162*)(lo + i + 2) = __halves2bfloat162(
        __float2bfloat16(v.z - __bfloat162float(h2)), __float2bfloat16(v.w - __bfloat162float(h3)));
    *(__half2*)(f16 + i)     = __halves2half2(__float2half_rn(v.x), __float2half_rn(v.y));
    *(__half2*)(f16 + i + 2) = __halves2half2(__float2half_rn(v.z), __float2half_rn(v.w));
}

__global__ __launch_bounds__(256)
void cvt16(const float* __restrict__ X, __half* __restrict__ o)
{
    const size_t i = ((size_t)blockIdx.x * 256 + threadIdx.x) << 2;
    float4 v = *(const float4*)(X + i);
    *(__half2*)(o + i)     = __halves2half2(__float2half_rn(v.x), __float2half_rn(v.y));
    *(__half2*)(o + i + 2) = __halves2half2(__float2half_rn(v.z), __float2half_rn(v.w));
}

__global__ void gmat(const float* __restrict__ W2,
                     __nv_bfloat16* __restrict__ Ghi, __nv_bfloat16* __restrict__ Glo)
{
    const int i = blockIdx.x, l = blockIdx.y, j = threadIdx.x;
    const float* W = W2 + (size_t)l * FD * RD;
    float a = 0.f;
    for (int d = 0; d < FD; ++d) a += W[(size_t)d * RD + i] * W[(size_t)d * RD + j];
    a *= SCALE;
    __nv_bfloat16 h = __float2bfloat16(a);
    const size_t o = (size_t)l * RD * RD + (size_t)i * RD + j;
    Ghi[o] = h;
    Glo[o] = __float2bfloat16(a - __bfloat162float(h));
}

__global__ void vvec(const float* __restrict__ W2, const float* __restrict__ b2,
                     float* __restrict__ v)
{
    const int l = blockIdx.x, r = threadIdx.x;
    const float* W = W2 + (size_t)l * FD * RD;
    const float* b = b2 + (size_t)l * FD;
    float a = 0.f;
    for (int d = 0; d < FD; ++d) a += W[(size_t)d * RD + r] * b[d];
    v[l * RD + r] = a * SCALE;
}

__global__ __launch_bounds__(256)
void cvec_k(const __half* __restrict__ Hhf, const float* __restrict__ v,
            float* __restrict__ cv)
{
    const int z = blockIdx.y;
    const int m = blockIdx.x * 256 + threadIdx.x;
    const __half* h = Hhf + (size_t)z * NH * RD + (size_t)m * RD;
    const float* vz = v + z * RD;
    float a = 0.f;
#pragma unroll
    for (int r = 0; r < RD; r += 2) {
        __half2 p = *(const __half2*)(h + r);
        a += __low2float(p) * vz[r] + __high2float(p) * vz[r + 1];
    }
    cv[(size_t)z * NH + m] = a;
}

// ======================================================================
extern "C" void kernel_launch(void* const* d_in, const int* in_sizes, int n_in,
                              void* d_out, int out_size)
{
    const float* cur  = (const float*)d_in[0];
    const float* hist = (const float*)d_in[1];
    const float* W1   = (const float*)d_in[2];
    const float* b1   = (const float*)d_in[3];
    const float* W2   = (const float*)d_in[4];
    const float* b2   = (const float*)d_in[5];
    const float* Wf   = (const float*)d_in[6];
    const float* bf   = (const float*)d_in[7];
    float* out = (float*)d_out;

    __nv_bfloat16 *Xhi, *Xlo, *W1hi, *W1lo, *Ghi, *Glo, *Hhi, *Hlo;
    __half *Wf16, *X16, *Hhf, *Hcf, *P, *VfT;
    float *v, *cv, *M, *Zp, *F;
    cudaGetSymbolAddress((void**)&Xhi, g_Xhi);   cudaGetSymbolAddress((void**)&Xlo, g_Xlo);
    cudaGetSymbolAddress((void**)&W1hi, g_W1hi); cudaGetSymbolAddress((void**)&W1lo, g_W1lo);
    cudaGetSymbolAddress((void**)&Ghi, g_Ghi);   cudaGetSymbolAddress((void**)&Glo, g_Glo);
    cudaGetSymbolAddress((void**)&Hhi, g_Hhi);   cudaGetSymbolAddress((void**)&Hlo, g_Hlo);
    cudaGetSymbolAddress((void**)&Wf16, g_Wf16); cudaGetSymbolAddress((void**)&X16, g_X16);
    cudaGetSymbolAddress((void**)&Hhf, g_Hhf);   cudaGetSymbolAddress((void**)&Hcf, g_Hcf);
    cudaGetSymbolAddress((void**)&P, g_P);       cudaGetSymbolAddress((void**)&VfT, g_VfT);
    cudaGetSymbolAddress((void**)&v, g_v);       cudaGetSymbolAddress((void**)&cv, g_cv);
    cudaGetSymbolAddress((void**)&M, g_M);       cudaGetSymbolAddress((void**)&Zp, g_Zp);
    cudaGetSymbolAddress((void**)&F, g_F);

    cudaFuncSetAttribute(mm128b<true,  1>, cudaFuncAttributeMaxDynamicSharedMemorySize, GSMEM_B);
    cudaFuncSetAttribute(mm128b<false, 2>, cudaFuncAttributeMaxDynamicSharedMemorySize, GSMEM_B);
    cudaFuncSetAttribute(vft_k,  cudaFuncAttributeMaxDynamicSharedMemorySize, GSMEM_V);
    cudaFuncSetAttribute(sexp_k, cudaFuncAttributeMaxDynamicSharedMemorySize, GSMEM_SX);
    cudaFuncSetAttribute(avz_k,  cudaFuncAttributeMaxDynamicSharedMemorySize, GSMEM_AV);

    // ---- preprocessing (single stream) ----
    split_rm<<<(NC * FD) / 1024, 256>>>(cur, Xhi, Xlo);
    split_h3<<<(NH * FD) / 1024, 256>>>(hist, Xhi + (size_t)NC * FD, Xlo + (size_t)NC * FD, X16);
    split_rm<<<(NL * RD * FD) / 1024, 256>>>(W1, W1hi, W1lo);
    cvt16<<<(FD * NL * FD) / 1024, 256>>>(Wf, Wf16);
    gmat<<<dim3(RD, NL), RD>>>(W2, Ghi, Glo);
    vvec<<<NL, RD>>>(W2, b2, v);

    // VfT_l = Wf_l @ hist^T  [FD, NH] fp16-1
    vft_k<<<dim3(NH / 128, FD / 128, NL), 256, GSMEM_V>>>(Wf16, X16, VfT);

    // H_l = relu(X @ W1_l^T + b1_l): split (rows<NC) + fp16 (rows>=NC)
    mm128b<true, 1><<<dim3(RD / 128, NT / 128, NL), 256, GSMEM_B>>>(
        Xhi, Xlo, 0, FD,
        W1hi, W1lo, (size_t)RD * FD, FD,
        b1, (size_t)RD,
        Hhi, Hlo, (size_t)NT * RD, RD,
        Hhf, (size_t)NH * RD, RD, FD);

    // cv[z] = Hhf[z] . v[z]
    cvec_k<<<dim3(NH / 256, NL), 256>>>(Hhf, v, cv);

    // Hc'_l = Hc_l @ G_l (pre-scaled)  [NC, RD] fp16
    mm128b<false, 2><<<dim3(RD / 128, NC / 128, NL), 256, GSMEM_B>>>(
        Hhi, Hlo, (size_t)NT * RD, RD,
        Ghi, Glo, (size_t)RD * RD, RD,
        nullptr, 0,
        nullptr, nullptr, 0, 0,
        Hcf, (size_t)NC * RD, RD, RD);

    // P = exp(s - m_tile); M, Zp partials
    sexp_k<<<dim3(NH / 128, NC / 128, NL), 256, GSMEM_SX>>>(Hcf, Hhf, cv, P, M, Zp);

    // normalized per-tile factors F = exp(M - m) / Z
    sfix<<<dim3(NC / 256, NL), 256>>>(M, Zp, F);

    // out = bf + sum_z sum_t F * (P_tile @ VfT^T)
    avz_k<<<dim3(FD / 128, NC / AV_BM), 256, GSMEM_AV>>>(P, VfT, F, bf, out);
}

// round 16
// speedup vs baseline: 1.6400x; 1.0536x over previous
#include <cuda_runtime.h>
#include <cuda_bf16.h>
#include <cuda_fp16.h>

#define NC 4096
#define NH 8192
#define NT 12288
#define FD 512
#define RD 128
#define NL 3
#define NTILE (NH / 128)          // 64 S-tiles per row

typedef unsigned long long u64;
typedef unsigned int u32;

#define KC 64                     // k elements per chunk
#define TILE_B 16384              // 128 rows x 64 elems x 2B
#define GSMEM_B (2 * 4 * TILE_B)  // bf16-3 kernel: 2 stages x 4 tiles = 128KB
#define GSMEM_SX (2 * 2 * TILE_B) // sexp: 2 stages x (A,B) = 64KB
#define GSMEM_V  (3 * 2 * TILE_B) // vft: 3 stages x (A,B) = 96KB

// AV kernel tiling (R10-proven configuration)
#define AV_BM 32
#define AV_BN 256
#define AV_TA (AV_BM * 128)            // 4KB
#define AV_TB (AV_BN * 128)            // 32KB
#define AV_STAGE (AV_TA + AV_TB)       // 36KB
#define GSMEM_AV (2 * AV_STAGE)        // 72KB

static const float SCALE = 0.044194173824159216f;  // 1/sqrt(512)

// ---------------- helpers ----------------
__device__ __forceinline__ u32 smem_u32(const void* p) {
    u32 a;
    asm("{ .reg .u64 t; cvta.to.shared.u64 t, %1; cvt.u32.u64 %0, t; }" : "=r"(a) : "l"(p));
    return a;
}
__device__ __forceinline__ void ldsm4(u32* r, u32 addr) {
    asm volatile("ldmatrix.sync.aligned.m8n8.x4.shared.b16 {%0,%1,%2,%3}, [%4];"
                 : "=r"(r[0]), "=r"(r[1]), "=r"(r[2]), "=r"(r[3]) : "r"(addr));
}
__device__ __forceinline__ void mma_bf16(float* c, const u32* a, const u32* b) {
    asm volatile("mma.sync.aligned.m16n8k16.row.col.f32.bf16.bf16.f32 "
                 "{%0,%1,%2,%3}, {%4,%5,%6,%7}, {%8,%9}, {%0,%1,%2,%3};"
                 : "+f"(c[0]), "+f"(c[1]), "+f"(c[2]), "+f"(c[3])
                 : "r"(a[0]), "r"(a[1]), "r"(a[2]), "r"(a[3]), "r"(b[0]), "r"(b[1]));
}
__device__ __forceinline__ void mma_f16(float* c, const u32* a, const u32* b) {
    asm volatile("mma.sync.aligned.m16n8k16.row.col.f32.f16.f16.f32 "
                 "{%0,%1,%2,%3}, {%4,%5,%6,%7}, {%8,%9}, {%0,%1,%2,%3};"
                 : "+f"(c[0]), "+f"(c[1]), "+f"(c[2]), "+f"(c[3])
                 : "r"(a[0]), "r"(a[1]), "r"(a[2]), "r"(a[3]), "r"(b[0]), "r"(b[1]));
}
__device__ __forceinline__ u32 swz(u32 base, u32 row, u32 k) {
    return base + row * 128 + ((((k >> 3) ^ (row & 7)) & 7) << 4);
}

// ---------------- scratch ----------------
__device__ __align__(128) __nv_bfloat16 g_Xhi[(size_t)NT * FD],  g_Xlo[(size_t)NT * FD];
__device__ __align__(128) __nv_bfloat16 g_W1hi[(size_t)NL * RD * FD], g_W1lo[(size_t)NL * RD * FD];
__device__ __align__(128) __nv_bfloat16 g_Ghi[(size_t)NL * RD * RD],  g_Glo[(size_t)NL * RD * RD];
__device__ __align__(128) __nv_bfloat16 g_Hhi[(size_t)NL * NT * RD],  g_Hlo[(size_t)NL * NT * RD];
__device__ __align__(128) __half        g_Wf16[(size_t)FD * NL * FD]; // Wf fp16
__device__ __align__(128) __half        g_X16 [(size_t)NH * FD];      // hist fp16
__device__ __align__(128) __half        g_Hhf[(size_t)NL * NH * RD];  // historical H, fp16
__device__ __align__(128) __half        g_Hcf[(size_t)NL * NC * RD];  // Hc*G*scale, fp16
__device__ __align__(128) __half        g_P  [(size_t)NL * NC * NH];  // exp(s - m_tile) per tile
__device__ __align__(128) float         g_M  [(size_t)NL * NTILE * NC];  // per-tile row max
__device__ __align__(128) float         g_Zp [(size_t)NL * NTILE * NC];  // per-tile row sums
__device__ __align__(128) float         g_F  [(size_t)NL * NTILE * NC];  // exp(M - m_row) / Z
__device__ __align__(128) __half        g_VfT[(size_t)NL * FD * NH];  // Wf_l @ hist^T
__device__ __align__(128) float         g_v  [NL * RD];
__device__ __align__(128) float         g_cv [NL * NH];

// ======================================================================
// Split-bf16 HMMA GEMM (3 products), z-batched: C = act(A@B^T + bias)
// OM 1: split out (rows<NC) + fp16 out (rows>=NC)   OM 2: fp16 out
// ======================================================================
template<bool RELU, int OM>
__global__ __launch_bounds__(256, 1)
void mm128b(const __nv_bfloat16* __restrict__ Ahi, const __nv_bfloat16* __restrict__ Alo,
            size_t zsA, int lda,
            const __nv_bfloat16* __restrict__ Bhi, const __nv_bfloat16* __restrict__ Blo,
            size_t zsB, int ldb,
            const float* __restrict__ bias, size_t zsBias,
            __nv_bfloat16* __restrict__ Chi, __nv_bfloat16* __restrict__ Clo,
            size_t zsC, int ldcs,
            __half* __restrict__ Ch, size_t zsCh, int ldch,
            int K)
{
    extern __shared__ __align__(1024) char smem[];
    const int tid  = threadIdx.x;
    const int wid  = tid >> 5;
    const int lane = tid & 31;
    const int z  = blockIdx.z;
    const int m0 = blockIdx.y * 128;
    const int n0 = blockIdx.x * 128;
    const int wm = (wid & 1) * 64;
    const int wn = (wid >> 1) * 32;

    const u32 sbase = smem_u32(smem);
    const __nv_bfloat16* srcs[4] = {
        Ahi + zsA * z + (size_t)m0 * lda, Alo + zsA * z + (size_t)m0 * lda,
        Bhi + zsB * z + (size_t)n0 * ldb, Blo + zsB * z + (size_t)n0 * ldb };
    const int lds[4] = { lda, lda, ldb, ldb };

    float acc[4][4][4];
#pragma unroll
    for (int i = 0; i < 4; ++i)
#pragma unroll
        for (int j = 0; j < 4; ++j)
#pragma unroll
            for (int h = 0; h < 4; ++h) acc[i][j][h] = 0.f;

    const u32 a_row = lane & 15;
    const u32 a_k   = (lane >> 4) << 3;
    const u32 b_row = ((lane >> 4) << 3) + (lane & 7);
    const u32 b_k   = ((lane >> 3) & 1) << 3;

    const int nch = K / KC;

    auto load_chunk = [&](int c, int buf) {
        const int kb = c * KC;
        const u32 sb = sbase + buf * 4 * TILE_B;
#pragma unroll
        for (int i = 0; i < 16; ++i) {
            const int t  = i >> 2;
            const int cc = ((i & 3) << 8) + tid;
            const int row = cc >> 3;
            const int k8  = cc & 7;
            const __nv_bfloat16* g = srcs[t] + (size_t)row * lds[t] + kb + (k8 << 3);
            const u32 d = sb + t * TILE_B + row * 128 + (((u32)k8 ^ ((u32)row & 7)) << 4);
            asm volatile("cp.async.cg.shared.global [%0], [%1], 16;" :: "r"(d), "l"(g));
        }
        asm volatile("cp.async.commit_group;" ::: "memory");
    };

    load_chunk(0, 0);

    for (int c = 0; c < nch; ++c) {
        if (c + 1 < nch) {
            load_chunk(c + 1, (c + 1) & 1);
            asm volatile("cp.async.wait_group 1;" ::: "memory");
        } else {
            asm volatile("cp.async.wait_group 0;" ::: "memory");
        }
        __syncthreads();

        const u32 sA_h = sbase + (c & 1) * 4 * TILE_B;
        const u32 sA_l = sA_h + TILE_B;
        const u32 sB_h = sA_h + 2 * TILE_B;
        const u32 sB_l = sA_h + 3 * TILE_B;

#pragma unroll
        for (int ks = 0; ks < 4; ++ks) {
            const u32 kb = ks << 4;
            u32 ah[4][4], al[4][4], bh[2][4], bl[2][4];
#pragma unroll
            for (int mt = 0; mt < 4; ++mt) {
                ldsm4(ah[mt], swz(sA_h, wm + mt * 16 + a_row, kb + a_k));
                ldsm4(al[mt], swz(sA_l, wm + mt * 16 + a_row, kb + a_k));
            }
#pragma unroll
            for (int np = 0; np < 2; ++np) {
                ldsm4(bh[np], swz(sB_h, wn + np * 16 + b_row, kb + b_k));
                ldsm4(bl[np], swz(sB_l, wn + np * 16 + b_row, kb + b_k));
            }
#pragma unroll
            for (int mt = 0; mt < 4; ++mt)
#pragma unroll
                for (int nt = 0; nt < 4; ++nt) {
                    const u32* bhp = &bh[nt >> 1][(nt & 1) * 2];
                    const u32* blp = &bl[nt >> 1][(nt & 1) * 2];
                    mma_bf16(acc[mt][nt], ah[mt], bhp);
                    mma_bf16(acc[mt][nt], ah[mt], blp);
                    mma_bf16(acc[mt][nt], al[mt], bhp);
                }
        }
        __syncthreads();
    }

    const int g  = lane >> 2;
    const int tg = lane & 3;
#pragma unroll
    for (int mt = 0; mt < 4; ++mt)
#pragma unroll
        for (int nt = 0; nt < 4; ++nt) {
            const int cc = n0 + wn + nt * 8 + tg * 2;
#pragma unroll
            for (int h = 0; h < 2; ++h) {
                const int r = m0 + wm + mt * 16 + g + h * 8;
                float v0 = acc[mt][nt][h * 2 + 0];
                float v1 = acc[mt][nt][h * 2 + 1];
                if (bias) { v0 += bias[zsBias * z + cc]; v1 += bias[zsBias * z + cc + 1]; }
                if (RELU) { v0 = fmaxf(v0, 0.f); v1 = fmaxf(v1, 0.f); }
                if (OM == 1) {
                    if (r < NC) {
                        __nv_bfloat16 h0 = __float2bfloat16(v0);
                        __nv_bfloat16 h1 = __float2bfloat16(v1);
                        *(__nv_bfloat162*)(Chi + zsC * z + (size_t)r * ldcs + cc) =
                            __halves2bfloat162(h0, h1);
                        *(__nv_bfloat162*)(Clo + zsC * z + (size_t)r * ldcs + cc) =
                            __halves2bfloat162(
                                __float2bfloat16(v0 - __bfloat162float(h0)),
                                __float2bfloat16(v1 - __bfloat162float(h1)));
                    } else {
                        *(__half2*)(Ch + zsCh * z + (size_t)(r - NC) * ldch + cc) =
                            __halves2half2(__float2half_rn(v0), __float2half_rn(v1));
                    }
                }
                if (OM == 2)
                    *(__half2*)(Ch + zsCh * z + (size_t)r * ldch + cc) =
                        __halves2half2(__float2half_rn(v0), __float2half_rn(v1));
            }
        }
}

// ======================================================================
// fp16 single-product GEMM for VfT: C[FD,NH] = Wf_l @ hist^T, fp16 out.
// ======================================================================
__global__ __launch_bounds__(256, 2)
void vft_k(const __half* __restrict__ A, const __half* __restrict__ B,
           __half* __restrict__ C)
{
    extern __shared__ __align__(1024) char smem[];
    const int tid  = threadIdx.x;
    const int wid  = tid >> 5;
    const int lane = tid & 31;
    const int z  = blockIdx.z;
    const int m0 = blockIdx.y * 128;     // FD rows
    const int n0 = blockIdx.x * 128;     // NH rows
    const int wm = (wid & 1) * 64;
    const int wn = (wid >> 1) * 32;

    const u32 sbase = smem_u32(smem);
    const __half* Asrc = A + (size_t)z * FD + (size_t)m0 * (NL * FD);  // lda = NL*FD
    const __half* Bsrc = B + (size_t)n0 * FD;                          // ldb = FD

    float acc[4][4][4];
#pragma unroll
    for (int i = 0; i < 4; ++i)
#pragma unroll
        for (int j = 0; j < 4; ++j)
#pragma unroll
            for (int h = 0; h < 4; ++h) acc[i][j][h] = 0.f;

    const u32 a_row = lane & 15;
    const u32 a_k   = (lane >> 4) << 3;
    const u32 b_row = ((lane >> 4) << 3) + (lane & 7);
    const u32 b_k   = ((lane >> 3) & 1) << 3;

    const int nch = FD / KC;   // 8

    auto load_chunk = [&](int c) {
        const int kb = c * KC;
        const u32 sb = sbase + (c % 3) * 2 * TILE_B;
#pragma unroll
        for (int i = 0; i < 8; ++i) {
            const int t  = i >> 2;
            const int cc = ((i & 3) << 8) + tid;
            const int row = cc >> 3;
            const int k8  = cc & 7;
            const __half* g = (t ? (Bsrc + (size_t)row * FD) : (Asrc + (size_t)row * (NL * FD)))
                              + kb + (k8 << 3);
            const u32 d = sb + t * TILE_B + row * 128 + (((u32)k8 ^ ((u32)row & 7)) << 4);
            asm volatile("cp.async.cg.shared.global [%0], [%1], 16;" :: "r"(d), "l"(g));
        }
        asm volatile("cp.async.commit_group;" ::: "memory");
    };

    load_chunk(0);
    load_chunk(1);

    for (int c = 0; c < nch; ++c) {
        if (c + 1 < nch) { asm volatile("cp.async.wait_group 1;" ::: "memory"); }
        else             { asm volatile("cp.async.wait_group 0;" ::: "memory"); }
        __syncthreads();
        if (c + 2 < nch) load_chunk(c + 2);

        const u32 sA = sbase + (c % 3) * 2 * TILE_B;
        const u32 sB = sA + TILE_B;
#pragma unroll
        for (int ks = 0; ks < 4; ++ks) {
            const u32 kb = ks << 4;
            u32 ah[4][4], bh[2][4];
#pragma unroll
            for (int mt = 0; mt < 4; ++mt)
                ldsm4(ah[mt], swz(sA, wm + mt * 16 + a_row, kb + a_k));
#pragma unroll
            for (int np = 0; np < 2; ++np)
                ldsm4(bh[np], swz(sB, wn + np * 16 + b_row, kb + b_k));
#pragma unroll
            for (int mt = 0; mt < 4; ++mt)
#pragma unroll
                for (int nt = 0; nt < 4; ++nt)
                    mma_f16(acc[mt][nt], ah[mt], &bh[nt >> 1][(nt & 1) * 2]);
        }
    }

    const int g  = lane >> 2;
    const int tg = lane & 3;
    __half* Cz = C + (size_t)z * FD * NH;
#pragma unroll
    for (int mt = 0; mt < 4; ++mt)
#pragma unroll
        for (int nt = 0; nt < 4; ++nt) {
            const int cc = n0 + wn + nt * 8 + tg * 2;
#pragma unroll
            for (int h = 0; h < 2; ++h) {
                const int r = m0 + wm + mt * 16 + g + h * 8;
                *(__half2*)(Cz + (size_t)r * NH + cc) =
                    __halves2half2(__float2half_rn(acc[mt][nt][h * 2 + 0]),
                                   __float2half_rn(acc[mt][nt][h * 2 + 1]));
            }
        }
}

// ======================================================================
// S+exp with per-tile row max (flash-style, overflow-proof):
// P_tile = exp(s - m_tile) fp16; M, Zp per (z, tile, row), no atomics.
// ======================================================================
__global__ __launch_bounds__(256, 2)
void sexp_k(const __half* __restrict__ Hcf, const __half* __restrict__ Hhf,
            const float* __restrict__ cv,
            __half* __restrict__ P, float* __restrict__ M, float* __restrict__ Zp)
{
    extern __shared__ __align__(1024) char smem[];
    __shared__ float wred[4][128];
    __shared__ float mrow[128];
    const int tid  = threadIdx.x;
    const int wid  = tid >> 5;
    const int lane = tid & 31;
    const int z  = blockIdx.z;
    const int m0 = blockIdx.y * 128;
    const int n0 = blockIdx.x * 128;
    const int wm = (wid & 1) * 64;
    const int wn = (wid >> 1) * 32;
    const int wcol = wid >> 1;

    const u32 sbase = smem_u32(smem);
    const __half* Asrc = Hcf + (size_t)z * NC * RD + (size_t)m0 * RD;
    const __half* Bsrc = Hhf + (size_t)z * NH * RD + (size_t)n0 * RD;

    float acc[4][4][4];
#pragma unroll
    for (int i = 0; i < 4; ++i)
#pragma unroll
        for (int j = 0; j < 4; ++j)
#pragma unroll
            for (int h = 0; h < 4; ++h) acc[i][j][h] = 0.f;

    const u32 a_row = lane & 15;
    const u32 a_k   = (lane >> 4) << 3;
    const u32 b_row = ((lane >> 4) << 3) + (lane & 7);
    const u32 b_k   = ((lane >> 3) & 1) << 3;

    auto load_chunk = [&](int c, int buf) {
        const int kb = c * KC;
        const u32 sb = sbase + buf * 2 * TILE_B;
#pragma unroll
        for (int i = 0; i < 8; ++i) {
            const int t  = i >> 2;
            const int cc = ((i & 3) << 8) + tid;
            const int row = cc >> 3;
            const int k8  = cc & 7;
            const __half* g = (t ? Bsrc : Asrc) + (size_t)row * RD + kb + (k8 << 3);
            const u32 d = sb + t * TILE_B + row * 128 + (((u32)k8 ^ ((u32)row & 7)) << 4);
            asm volatile("cp.async.cg.shared.global [%0], [%1], 16;" :: "r"(d), "l"(g));
        }
        asm volatile("cp.async.commit_group;" ::: "memory");
    };

    load_chunk(0, 0);

    for (int c = 0; c < 2; ++c) {
        if (c == 0) {
            load_chunk(1, 1);
            asm volatile("cp.async.wait_group 1;" ::: "memory");
        } else {
            asm volatile("cp.async.wait_group 0;" ::: "memory");
        }
        __syncthreads();

        const u32 sA = sbase + (c & 1) * 2 * TILE_B;
        const u32 sB = sA + TILE_B;
#pragma unroll
        for (int ks = 0; ks < 4; ++ks) {
            const u32 kb = ks << 4;
            u32 ah[4][4], bh[2][4];
#pragma unroll
            for (int mt = 0; mt < 4; ++mt)
                ldsm4(ah[mt], swz(sA, wm + mt * 16 + a_row, kb + a_k));
#pragma unroll
            for (int np = 0; np < 2; ++np)
                ldsm4(bh[np], swz(sB, wn + np * 16 + b_row, kb + b_k));
#pragma unroll
            for (int mt = 0; mt < 4; ++mt)
#pragma unroll
                for (int nt = 0; nt < 4; ++nt)
                    mma_f16(acc[mt][nt], ah[mt], &bh[nt >> 1][(nt & 1) * 2]);
        }
        __syncthreads();
    }

    const int g  = lane >> 2;
    const int tg = lane & 3;
    const float* cvz = cv + (size_t)z * NH;

#pragma unroll
    for (int nt = 0; nt < 4; ++nt) {
        const int cc = n0 + wn + nt * 8 + tg * 2;
        float2 cb = *(const float2*)(cvz + cc);
#pragma unroll
        for (int mt = 0; mt < 4; ++mt)
#pragma unroll
            for (int h = 0; h < 2; ++h) {
                acc[mt][nt][h * 2 + 0] += cb.x;
                acc[mt][nt][h * 2 + 1] += cb.y;
            }
    }

    // per-row tile max
#pragma unroll
    for (int mt = 0; mt < 4; ++mt)
#pragma unroll
        for (int h = 0; h < 2; ++h) {
            float mx = -1e30f;
#pragma unroll
            for (int nt = 0; nt < 4; ++nt)
                mx = fmaxf(mx, fmaxf(acc[mt][nt][h * 2], acc[mt][nt][h * 2 + 1]));
            mx = fmaxf(mx, __shfl_xor_sync(0xFFFFFFFFu, mx, 1));
            mx = fmaxf(mx, __shfl_xor_sync(0xFFFFFFFFu, mx, 2));
            if (tg == 0) wred[wcol][wm + mt * 16 + g + h * 8] = mx;
        }
    __syncthreads();
    if (tid < 128)
        mrow[tid] = fmaxf(fmaxf(wred[0][tid], wred[1][tid]),
                          fmaxf(wred[2][tid], wred[3][tid]));
    __syncthreads();

    __half* Pz = P + (size_t)z * NC * NH;
#pragma unroll
    for (int mt = 0; mt < 4; ++mt)
#pragma unroll
        for (int h = 0; h < 2; ++h) {
            const int lr = wm + mt * 16 + g + h * 8;
            const int r = m0 + lr;
            const float m = mrow[lr];
            float rowacc = 0.f;
#pragma unroll
            for (int nt = 0; nt < 4; ++nt) {
                const int cc = n0 + wn + nt * 8 + tg * 2;
                float e0 = __expf(acc[mt][nt][h * 2 + 0] - m);
                float e1 = __expf(acc[mt][nt][h * 2 + 1] - m);
                *(__half2*)(Pz + (size_t)r * NH + cc) =
                    __halves2half2(__float2half_rn(e0), __float2half_rn(e1));
                rowacc += e0 + e1;
            }
            rowacc += __shfl_xor_sync(0xFFFFFFFFu, rowacc, 1);
            rowacc += __shfl_xor_sync(0xFFFFFFFFu, rowacc, 2);
            if (tg == 0) wred[wcol][lr] = rowacc;
        }
    __syncthreads();
    if (tid < 128) {
        const size_t o = ((size_t)z * NTILE + blockIdx.x) * NC + m0 + tid;
        M[o]  = mrow[tid];
        Zp[o] = wred[0][tid] + wred[1][tid] + wred[2][tid] + wred[3][tid];
    }
}

// per-row global max + normalized per-tile factors F = exp(M-m)/Z. grid (NC/256, NL).
__global__ __launch_bounds__(256)
void sfix(const float* __restrict__ M, const float* __restrict__ Zp,
          float* __restrict__ F)
{
    const int z = blockIdx.y;
    const int r = blockIdx.x * 256 + threadIdx.x;
    float m = -1e30f;
    for (int t = 0; t < NTILE; ++t)
        m = fmaxf(m, M[((size_t)z * NTILE + t) * NC + r]);
    float zs = 0.f;
    for (int t = 0; t < NTILE; ++t) {
        const size_t o = ((size_t)z * NTILE + t) * NC + r;
        zs += Zp[o] * __expf(M[o] - m);
    }
    const float inv = 1.f / zs;
    for (int t = 0; t < NTILE; ++t) {
        const size_t o = ((size_t)z * NTILE + t) * NC + r;
        F[o] = __expf(M[o] - m) * inv;
    }
}

// ======================================================================
// Fused AV over all levels with factor folding (R10-proven form):
// out[r][n] = bf[n] + sum_z sum_t F[z][t][r] * (P_tile @ VfT_z^T)
// CTA 32x256, K flat over (z, chunks), 2-stage, 256 threads, 2 CTAs/SM.
// Per 128-col tile (2 chunks): accumulate in acc2, flush acc += acc2*F (f32).
// ======================================================================
__global__ __launch_bounds__(256, 2)
void avz_k(const __half* __restrict__ P, const __half* __restrict__ VfT,
           const float* __restrict__ Fz, const float* __restrict__ bf,
           float* __restrict__ out)
{
    extern __shared__ __align__(1024) char smem[];
    __shared__ float Fs[NL * NTILE * AV_BM];   // 24KB
    const int tid  = threadIdx.x;
    const int wid  = tid >> 5;
    const int lane = tid & 31;
    const int n0 = blockIdx.x * AV_BN;
    const int m0 = blockIdx.y * AV_BM;
    const int wn = wid * 32;

    // preload normalized factors for this row band
    for (int i = tid; i < NL * NTILE * AV_BM; i += 256) {
        const int zt = i / AV_BM;
        const int r  = i - zt * AV_BM;
        Fs[i] = Fz[(size_t)zt * NC + m0 + r];
    }

    const u32 sbase = smem_u32(smem);

    float acc[2][4][4], acc2[2][4][4];
#pragma unroll
    for (int i = 0; i < 2; ++i)
#pragma unroll
        for (int j = 0; j < 4; ++j)
#pragma unroll
            for (int h = 0; h < 4; ++h) { acc[i][j][h] = 0.f; acc2[i][j][h] = 0.f; }

    const u32 a_row = lane & 15;
    const u32 a_k   = (lane >> 4) << 3;
    const u32 b_row = ((lane >> 4) << 3) + (lane & 7);
    const u32 b_k   = ((lane >> 3) & 1) << 3;

    const int arow_l = tid >> 3;
    const int ak8    = tid & 7;
    const u32 a_off  = (u32)arow_l * 128 + ((((u32)ak8) ^ ((u32)arow_l & 7)) << 4);

    auto load_chunk = [&](int cg) {
        const int z = cg >> 7;
        const int c = cg & 127;
        const int kb = c * KC;
        const u32 sb = sbase + (cg & 1) * AV_STAGE;
        {   // A: 32 rows x 64 halves, one shot
            const __half* g = P + (size_t)z * NC * NH + (size_t)(m0 + arow_l) * NH
                            + kb + (ak8 << 3);
            asm volatile("cp.async.cg.shared.global [%0], [%1], 16;"
                         :: "r"(sb + a_off), "l"(g));
        }
#pragma unroll
        for (int i = 0; i < 8; ++i) {   // B: 256 rows x 64 halves
            const int cc = i * 256 + tid;
            const int row = cc >> 3;
            const int k8  = cc & 7;
            const __half* g = VfT + (size_t)z * FD * NH + (size_t)(n0 + row) * NH
                            + kb + (k8 << 3);
            const u32 d = sb + AV_TA + row * 128 + (((u32)k8 ^ ((u32)row & 7)) << 4);
            asm volatile("cp.async.cg.shared.global [%0], [%1], 16;" :: "r"(d), "l"(g));
        }
        asm volatile("cp.async.commit_group;" ::: "memory");
    };

    __syncthreads();     // Fs ready
    const int NCHG = NL * (NH / KC);   // 384
    load_chunk(0);

    const int g  = lane >> 2;
    const int tg = lane & 3;

    for (int cg = 0; cg < NCHG; ++cg) {
        if (cg + 1 < NCHG) {
            load_chunk(cg + 1);
            asm volatile("cp.async.wait_group 1;" ::: "memory");
        } else {
            asm volatile("cp.async.wait_group 0;" ::: "memory");
        }
        __syncthreads();

        const u32 sA = sbase + (cg & 1) * AV_STAGE;
        const u32 sB = sA + AV_TA;
#pragma unroll
        for (int ks = 0; ks < 4; ++ks) {
            const u32 kb = ks << 4;
            u32 ah[2][4], bh[2][4];
#pragma unroll
            for (int mt = 0; mt < 2; ++mt)
                ldsm4(ah[mt], swz(sA, mt * 16 + a_row, kb + a_k));
#pragma unroll
            for (int np = 0; np < 2; ++np)
                ldsm4(bh[np], swz(sB, wn + np * 16 + b_row, kb + b_k));
#pragma unroll
            for (int mt = 0; mt < 2; ++mt)
#pragma unroll
                for (int nt = 0; nt < 4; ++nt)
                    mma_f16(acc2[mt][nt], ah[mt], &bh[nt >> 1][(nt & 1) * 2]);
        }
        __syncthreads();

        if (cg & 1) {   // flush 128-col tile: acc += acc2 * F[z][t][row]
            const int z = cg >> 7;
            const int t = (cg & 127) >> 1;
            const int base = (z * NTILE + t) * AV_BM;
#pragma unroll
            for (int mt = 0; mt < 2; ++mt)
#pragma unroll
                for (int h = 0; h < 2; ++h) {
                    const float f = Fs[base + mt * 16 + g + h * 8];
#pragma unroll
                    for (int nt = 0; nt < 4; ++nt) {
                        acc[mt][nt][h * 2 + 0] = fmaf(acc2[mt][nt][h * 2 + 0], f,
                                                      acc[mt][nt][h * 2 + 0]);
                        acc[mt][nt][h * 2 + 1] = fmaf(acc2[mt][nt][h * 2 + 1], f,
                                                      acc[mt][nt][h * 2 + 1]);
                        acc2[mt][nt][h * 2 + 0] = 0.f;
                        acc2[mt][nt][h * 2 + 1] = 0.f;
                    }
                }
        }
    }

#pragma unroll
    for (int mt = 0; mt < 2; ++mt)
#pragma unroll
        for (int nt = 0; nt < 4; ++nt) {
            const int cc = n0 + wn + nt * 8 + tg * 2;
            const float2 b = *(const float2*)(bf + cc);
#pragma unroll
            for (int h = 0; h < 2; ++h) {
                const int r = m0 + mt * 16 + g + h * 8;
                *(float2*)(out + (size_t)r * FD + cc) =
                    make_float2(acc[mt][nt][h * 2 + 0] + b.x,
                                acc[mt][nt][h * 2 + 1] + b.y);
            }
        }
}

// ---------------- small kernels ----------------
__global__ __launch_bounds__(256)
void split_rm(const float* __restrict__ X,
              __nv_bfloat16* __restrict__ hi, __nv_bfloat16* __restrict__ lo)
{
    const size_t i = ((size_t)blockIdx.x * 256 + threadIdx.x) << 2;
    float4 v = *(const float4*)(X + i);
    __nv_bfloat16 h0 = __float2bfloat16(v.x), h1 = __float2bfloat16(v.y);
    __nv_bfloat16 h2 = __float2bfloat16(v.z), h3 = __float2bfloat16(v.w);
    *(__nv_bfloat162*)(hi + i)     = __halves2bfloat162(h0, h1);
    *(__nv_bfloat162*)(hi + i + 2) = __halves2bfloat162(h2, h3);
    *(__nv_bfloat162*)(lo + i)     = __halves2bfloat162(
        __float2bfloat16(v.x - __bfloat162float(h0)), __float2bfloat16(v.y - __bfloat162float(h1)));
    *(__nv_bfloat162*)(lo + i + 2) = __halves2bfloat162(
        __float2bfloat16(v.z - __bfloat162float(h2)), __float2bfloat16(v.w - __bfloat162float(h3)));
}

// hist: one read -> bf16 split + fp16 copy
__global__ __launch_bounds__(256)
void split_h3(const float* __restrict__ X,
              __nv_bfloat16* __restrict__ hi, __nv_bfloat16* __restrict__ lo,
              __half* __restrict__ f16)
{
    const size_t i = ((size_t)blockIdx.x * 256 + threadIdx.x) << 2;
    float4 v = *(const float4*)(X + i);
    __nv_bfloat16 h0 = __float2bfloat16(v.x), h1 = __float2bfloat16(v.y);
    __nv_bfloat16 h2 = __float2bfloat16(v.z), h3 = __float2bfloat16(v.w);
    *(__nv_bfloat162*)(hi + i)     = __halves2bfloat162(h0, h1);
    *(__nv_bfloat162*)(hi + i + 2) = __halves2bfloat162(h2, h3);
    *(__nv_bfloat162*)(lo + i)     = __halves2bfloat162(
        __float2bfloat16(v.x - __bfloat162float(h0)), __float2bfloat16(v.y - __bfloat162float(h1)));
    *(__nv_bfloat162*)(lo + i + 2) = __halves2bfloat162(
        __float2bfloat16(v.z - __bfloat162float(h2)), __float2bfloat16(v.w - __bfloat162float(h3)));
    *(__half2*)(f16 + i)     = __halves2half2(__float2half_rn(v.x), __float2half_rn(v.y));
    *(__half2*)(f16 + i + 2) = __halves2half2(__float2half_rn(v.z), __float2half_rn(v.w));
}

__global__ __launch_bounds__(256)
void cvt16(const float* __restrict__ X, __half* __restrict__ o)
{
    const size_t i = ((size_t)blockIdx.x * 256 + threadIdx.x) << 2;
    float4 v = *(const float4*)(X + i);
    *(__half2*)(o + i)     = __halves2half2(__float2half_rn(v.x), __float2half_rn(v.y));
    *(__half2*)(o + i + 2) = __halves2half2(__float2half_rn(v.z), __float2half_rn(v.w));
}

__global__ void gmat(const float* __restrict__ W2,
                     __nv_bfloat16* __restrict__ Ghi, __nv_bfloat16* __restrict__ Glo)
{
    const int i = blockIdx.x, l = blockIdx.y, j = threadIdx.x;
    const float* W = W2 + (size_t)l * FD * RD;
    float a = 0.f;
    for (int d = 0; d < FD; ++d) a += W[(size_t)d * RD + i] * W[(size_t)d * RD + j];
    a *= SCALE;
    __nv_bfloat16 h = __float2bfloat16(a);
    const size_t o = (size_t)l * RD * RD + (size_t)i * RD + j;
    Ghi[o] = h;
    Glo[o] = __float2bfloat16(a - __bfloat162float(h));
}

__global__ void vvec(const float* __restrict__ W2, const float* __restrict__ b2,
                     float* __restrict__ v)
{
    const int l = blockIdx.x, r = threadIdx.x;
    const float* W = W2 + (size_t)l * FD * RD;
    const float* b = b2 + (size_t)l * FD;
    float a = 0.f;
    for (int d = 0; d < FD; ++d) a += W[(size_t)d * RD + r] * b[d];
    v[l * RD + r] = a * SCALE;
}

__global__ __launch_bounds__(256)
void cvec_k(const __half* __restrict__ Hhf, const float* __restrict__ v,
            float* __restrict__ cv)
{
    const int z = blockIdx.y;
    const int m = blockIdx.x * 256 + threadIdx.x;
    const __half* h = Hhf + (size_t)z * NH * RD + (size_t)m * RD;
    const float* vz = v + z * RD;
    float a = 0.f;
#pragma unroll
    for (int r = 0; r < RD; r += 2) {
        __half2 p = *(const __half2*)(h + r);
        a += __low2float(p) * vz[r] + __high2float(p) * vz[r + 1];
    }
    cv[(size_t)z * NH + m] = a;
}

// ======================================================================
extern "C" void kernel_launch(void* const* d_in, const int* in_sizes, int n_in,
                              void* d_out, int out_size)
{
    const float* cur  = (const float*)d_in[0];
    const float* hist = (const float*)d_in[1];
    const float* W1   = (const float*)d_in[2];
    const float* b1   = (const float*)d_in[3];
    const float* W2   = (const float*)d_in[4];
    const float* b2   = (const float*)d_in[5];
    const float* Wf   = (const float*)d_in[6];
    const float* bf   = (const float*)d_in[7];
    float* out = (float*)d_out;

    __nv_bfloat16 *Xhi, *Xlo, *W1hi, *W1lo, *Ghi, *Glo, *Hhi, *Hlo;
    __half *Wf16, *X16, *Hhf, *Hcf, *P, *VfT;
    float *v, *cv, *M, *Zp, *F;
    cudaGetSymbolAddress((void**)&Xhi, g_Xhi);   cudaGetSymbolAddress((void**)&Xlo, g_Xlo);
    cudaGetSymbolAddress((void**)&W1hi, g_W1hi); cudaGetSymbolAddress((void**)&W1lo, g_W1lo);
    cudaGetSymbolAddress((void**)&Ghi, g_Ghi);   cudaGetSymbolAddress((void**)&Glo, g_Glo);
    cudaGetSymbolAddress((void**)&Hhi, g_Hhi);   cudaGetSymbolAddress((void**)&Hlo, g_Hlo);
    cudaGetSymbolAddress((void**)&Wf16, g_Wf16); cudaGetSymbolAddress((void**)&X16, g_X16);
    cudaGetSymbolAddress((void**)&Hhf, g_Hhf);   cudaGetSymbolAddress((void**)&Hcf, g_Hcf);
    cudaGetSymbolAddress((void**)&P, g_P);       cudaGetSymbolAddress((void**)&VfT, g_VfT);
    cudaGetSymbolAddress((void**)&v, g_v);       cudaGetSymbolAddress((void**)&cv, g_cv);
    cudaGetSymbolAddress((void**)&M, g_M);       cudaGetSymbolAddress((void**)&Zp, g_Zp);
    cudaGetSymbolAddress((void**)&F, g_F);

    cudaFuncSetAttribute(mm128b<true,  1>, cudaFuncAttributeMaxDynamicSharedMemorySize, GSMEM_B);
    cudaFuncSetAttribute(mm128b<false, 2>, cudaFuncAttributeMaxDynamicSharedMemorySize, GSMEM_B);
    cudaFuncSetAttribute(vft_k,  cudaFuncAttributeMaxDynamicSharedMemorySize, GSMEM_V);
    cudaFuncSetAttribute(sexp_k, cudaFuncAttributeMaxDynamicSharedMemorySize, GSMEM_SX);
    cudaFuncSetAttribute(avz_k,  cudaFuncAttributeMaxDynamicSharedMemorySize, GSMEM_AV);

    // ---- preprocessing (single stream) ----
    split_rm<<<(NC * FD) / 1024, 256>>>(cur, Xhi, Xlo);
    split_h3<<<(NH * FD) / 1024, 256>>>(hist, Xhi + (size_t)NC * FD, Xlo + (size_t)NC * FD, X16);
    split_rm<<<(NL * RD * FD) / 1024, 256>>>(W1, W1hi, W1lo);
    cvt16<<<(FD * NL * FD) / 1024, 256>>>(Wf, Wf16);
    gmat<<<dim3(RD, NL), RD>>>(W2, Ghi, Glo);
    vvec<<<NL, RD>>>(W2, b2, v);

    // VfT_l = Wf_l @ hist^T  [FD, NH] fp16-1
    vft_k<<<dim3(NH / 128, FD / 128, NL), 256, GSMEM_V>>>(Wf16, X16, VfT);

    // H_l = relu(X @ W1_l^T + b1_l): split (rows<NC) + fp16 (rows>=NC)
    mm128b<true, 1><<<dim3(RD / 128, NT / 128, NL), 256, GSMEM_B>>>(
        Xhi, Xlo, 0, FD,
        W1hi, W1lo, (size_t)RD * FD, FD,
        b1, (size_t)RD,
        Hhi, Hlo, (size_t)NT * RD, RD,
        Hhf, (size_t)NH * RD, RD, FD);

    // cv[z] = Hhf[z] . v[z]
    cvec_k<<<dim3(NH / 256, NL), 256>>>(Hhf, v, cv);

    // Hc'_l = Hc_l @ G_l (pre-scaled)  [NC, RD] fp16
    mm128b<false, 2><<<dim3(RD / 128, NC / 128, NL), 256, GSMEM_B>>>(
        Hhi, Hlo, (size_t)NT * RD, RD,
        Ghi, Glo, (size_t)RD * RD, RD,
        nullptr, 0,
        nullptr, nullptr, 0, 0,
        Hcf, (size_t)NC * RD, RD, RD);

    // P = exp(s - m_tile); M, Zp partials
    sexp_k<<<dim3(NH / 128, NC / 128, NL), 256, GSMEM_SX>>>(Hcf, Hhf, cv, P, M, Zp);

    // normalized per-tile factors F = exp(M - m) / Z
    sfix<<<dim3(NC / 256, NL), 256>>>(M, Zp, F);

    // out = bf + sum_z sum_t F * (P_tile @ VfT^T)
    avz_k<<<dim3(FD / AV_BN, NC / AV_BM), 256, GSMEM_AV>>>(P, VfT, F, bf, out);
}